// round 1
// baseline (speedup 1.0000x reference)
#include <cuda_runtime.h>
#include <math.h>

// ---------------------------------------------------------------------------
// Problem constants: B=8, C=512, H=W=96, heads=8, dh=64
// seq layout: [768, 96, 512]  (n = b*96 + w, t = h, channel c)
// ---------------------------------------------------------------------------
#define TOTE 37748736  // 768*96*512 == 8*512*96*96

__device__ float g_bufs[5][TOTE];
__device__ float g_bnscale[512];
__device__ float g_bnbias[512];

// Fast exp via degree-6 poly on 2^f (FMA-only, avoids MUFU bottleneck).
// Valid for x <= ~0 after max subtraction; rel err ~1e-5.
__device__ __forceinline__ float fast_exp(float x) {
    x = fmaxf(x, -87.0f);
    float t = x * 1.44269504088896f;
    float fi = floorf(t);
    float f = t - fi;
    float p = 1.54035304e-4f;
    p = fmaf(p, f, 1.33335581e-3f);
    p = fmaf(p, f, 9.61812910e-3f);
    p = fmaf(p, f, 5.55041087e-2f);
    p = fmaf(p, f, 2.40226507e-1f);
    p = fmaf(p, f, 6.93147181e-1f);
    p = fmaf(p, f, 1.0f);
    return p * __int_as_float(((int)fi + 127) << 23);
}

// ---------------------------------------------------------------------------
// Layout transposes: per (b,h) plane, transpose (c <-> w), 32x32 smem tiles
// ---------------------------------------------------------------------------
// img [b,c,h,w] -> seq [(b*96+w)*96 + h, c]
__global__ void img2seq(const float* __restrict__ img, float* __restrict__ seq) {
    __shared__ float tile[32][33];
    int bh = blockIdx.z;
    int b = bh / 96, h = bh % 96;
    int c0 = blockIdx.y * 32, w0 = blockIdx.x * 32;
    int tx = threadIdx.x, ty = threadIdx.y;
#pragma unroll
    for (int i = 0; i < 4; i++) {
        int c = c0 + ty + i * 8;
        tile[ty + i * 8][tx] = img[(((size_t)b * 512 + c) * 96 + h) * 96 + w0 + tx];
    }
    __syncthreads();
#pragma unroll
    for (int i = 0; i < 4; i++) {
        int w = w0 + ty + i * 8;
        seq[(((size_t)(b * 96 + w)) * 96 + h) * 512 + c0 + tx] = tile[tx][ty + i * 8];
    }
}

// seq [(b*96+w)*96 + h, c] -> img [b,c,h,w]
__global__ void seq2img(const float* __restrict__ seq, float* __restrict__ img) {
    __shared__ float tile[32][33];
    int bh = blockIdx.z;
    int b = bh / 96, h = bh % 96;
    int c0 = blockIdx.y * 32, w0 = blockIdx.x * 32;
    int tx = threadIdx.x, ty = threadIdx.y;
#pragma unroll
    for (int i = 0; i < 4; i++) {
        int w = w0 + ty + i * 8;
        tile[ty + i * 8][tx] = seq[(((size_t)(b * 96 + w)) * 96 + h) * 512 + c0 + tx];
    }
    __syncthreads();
#pragma unroll
    for (int i = 0; i < 4; i++) {
        int c = c0 + ty + i * 8;
        img[(((size_t)b * 512 + c) * 96 + h) * 96 + w0 + tx] = tile[tx][ty + i * 8];
    }
}

// ---------------------------------------------------------------------------
// GEMM: C[M,512] = A[M,512] @ W[512,512]^T  (+A | +bias)
// BM=128 BN=64 BK=16, 256 threads, 8x4 register tile.
// mode 0: plain; 1: +Add[m,n]; 2: +bias[n]
// ---------------------------------------------------------------------------
__global__ __launch_bounds__(256) void gemm_nt512(
    const float* __restrict__ A, const float* __restrict__ W,
    const float* __restrict__ Add, const float* __restrict__ bias,
    float* __restrict__ Cout, int mode)
{
    __shared__ float As[16][136];
    __shared__ float Bs[16][68];
    int m0 = blockIdx.y * 128;
    int n0 = blockIdx.x * 64;
    int tid = threadIdx.x;
    int tx = tid & 15, ty = tid >> 4;
    float acc[8][4];
#pragma unroll
    for (int i = 0; i < 8; i++)
#pragma unroll
        for (int j = 0; j < 4; j++) acc[i][j] = 0.f;

    for (int k0 = 0; k0 < 512; k0 += 16) {
#pragma unroll
        for (int r = 0; r < 2; r++) {
            int id = tid * 2 + r;
            int row = id >> 2, c4 = (id & 3) * 4;
            float4 v = *(const float4*)(A + (size_t)(m0 + row) * 512 + k0 + c4);
            As[c4 + 0][row] = v.x; As[c4 + 1][row] = v.y;
            As[c4 + 2][row] = v.z; As[c4 + 3][row] = v.w;
        }
        {
            int row = tid >> 2, c4 = (tid & 3) * 4;
            float4 v = *(const float4*)(W + (size_t)(n0 + row) * 512 + k0 + c4);
            Bs[c4 + 0][row] = v.x; Bs[c4 + 1][row] = v.y;
            Bs[c4 + 2][row] = v.z; Bs[c4 + 3][row] = v.w;
        }
        __syncthreads();
#pragma unroll
        for (int kk = 0; kk < 16; kk++) {
            float4 a0 = *(const float4*)&As[kk][ty * 8];
            float4 a1 = *(const float4*)&As[kk][ty * 8 + 4];
            float4 b  = *(const float4*)&Bs[kk][tx * 4];
            float am[8] = {a0.x, a0.y, a0.z, a0.w, a1.x, a1.y, a1.z, a1.w};
            float bn[4] = {b.x, b.y, b.z, b.w};
#pragma unroll
            for (int i = 0; i < 8; i++)
#pragma unroll
                for (int j = 0; j < 4; j++)
                    acc[i][j] = fmaf(am[i], bn[j], acc[i][j]);
        }
        __syncthreads();
    }
    int nb = n0 + tx * 4;
#pragma unroll
    for (int i = 0; i < 8; i++) {
        int m = m0 + ty * 8 + i;
        float4 o;
        o.x = acc[i][0]; o.y = acc[i][1]; o.z = acc[i][2]; o.w = acc[i][3];
        if (mode == 1) {
            float4 ad = *(const float4*)(Add + (size_t)m * 512 + nb);
            o.x += ad.x; o.y += ad.y; o.z += ad.z; o.w += ad.w;
        } else if (mode == 2) {
            float4 bb = *(const float4*)(bias + nb);
            o.x += bb.x; o.y += bb.y; o.z += bb.z; o.w += bb.w;
        }
        *(float4*)(Cout + (size_t)m * 512 + nb) = o;
    }
}

// ---------------------------------------------------------------------------
// Attention: one block per (n, head). T=96, dh=64. fp32, fast_exp softmax,
// normalization folded into PV epilogue.
// ---------------------------------------------------------------------------
__global__ __launch_bounds__(256) void attn_kernel(
    const float* __restrict__ Qg, const float* __restrict__ Kg,
    const float* __restrict__ Vg, float* __restrict__ Og)
{
    extern __shared__ float sm[];
    float* Qs = sm;                       // 96 x 65
    float* Ks = sm + 96 * 65;             // 96 x 65
    float* Vs = sm + 2 * 96 * 65;         // 96 x 68
    float* S  = sm + 2 * 96 * 65 + 96 * 68;  // 96 x 97
    __shared__ float rowred[96];
    __shared__ float part[96][2];

    int hd = blockIdx.x, n = blockIdx.y;
    size_t base = (size_t)n * 96 * 512 + hd * 64;
    const float* qb = Qg + base;
    const float* kb = Kg + base;
    const float* vb = Vg + base;
    int tid = threadIdx.x;

    for (int i = tid; i < 96 * 16; i += 256) {
        int r = i >> 4, c = (i & 15) * 4;
        float4 q = *(const float4*)(qb + (size_t)r * 512 + c);
        float4 k = *(const float4*)(kb + (size_t)r * 512 + c);
        float4 v = *(const float4*)(vb + (size_t)r * 512 + c);
        Qs[r * 65 + c] = q.x; Qs[r * 65 + c + 1] = q.y; Qs[r * 65 + c + 2] = q.z; Qs[r * 65 + c + 3] = q.w;
        Ks[r * 65 + c] = k.x; Ks[r * 65 + c + 1] = k.y; Ks[r * 65 + c + 2] = k.z; Ks[r * 65 + c + 3] = k.w;
        Vs[r * 68 + c] = v.x; Vs[r * 68 + c + 1] = v.y; Vs[r * 68 + c + 2] = v.z; Vs[r * 68 + c + 3] = v.w;
    }
    __syncthreads();

    int tx = tid & 15, ty = tid >> 4;
    int qr = ty * 6, kr = tx * 6;
    {
        float acc[6][6];
#pragma unroll
        for (int i = 0; i < 6; i++)
#pragma unroll
            for (int j = 0; j < 6; j++) acc[i][j] = 0.f;
        for (int k = 0; k < 64; k++) {
            float qv[6], kv[6];
#pragma unroll
            for (int i = 0; i < 6; i++) qv[i] = Qs[(qr + i) * 65 + k];
#pragma unroll
            for (int j = 0; j < 6; j++) kv[j] = Ks[(kr + j) * 65 + k];
#pragma unroll
            for (int i = 0; i < 6; i++)
#pragma unroll
                for (int j = 0; j < 6; j++)
                    acc[i][j] = fmaf(qv[i], kv[j], acc[i][j]);
        }
#pragma unroll
        for (int i = 0; i < 6; i++)
#pragma unroll
            for (int j = 0; j < 6; j++)
                S[(qr + i) * 97 + kr + j] = acc[i][j] * 0.125f;
    }
    __syncthreads();

    // row max (2 threads per row)
    if (tid < 192) {
        int r = tid >> 1, hf = (tid & 1) * 48;
        float m = -1e30f;
        for (int c = 0; c < 48; c++) m = fmaxf(m, S[r * 97 + hf + c]);
        part[r][tid & 1] = m;
    }
    __syncthreads();
    if (tid < 96) rowred[tid] = fmaxf(part[tid][0], part[tid][1]);
    __syncthreads();
    // exp (all 256 threads)
    for (int i = tid; i < 96 * 96; i += 256) {
        int r = i / 96, c = i - r * 96;
        S[r * 97 + c] = fast_exp(S[r * 97 + c] - rowred[r]);
    }
    __syncthreads();
    // row sums
    if (tid < 192) {
        int r = tid >> 1, hf = (tid & 1) * 48;
        float s = 0.f;
        for (int c = 0; c < 48; c++) s += S[r * 97 + hf + c];
        part[r][tid & 1] = s;
    }
    __syncthreads();
    if (tid < 96) rowred[tid] = part[tid][0] + part[tid][1];
    __syncthreads();

    // O = (S @ V) / rowsum
    float o[6][4];
#pragma unroll
    for (int i = 0; i < 6; i++)
#pragma unroll
        for (int j = 0; j < 4; j++) o[i][j] = 0.f;
    for (int k = 0; k < 96; k++) {
        float4 v = *(const float4*)&Vs[k * 68 + tx * 4];
#pragma unroll
        for (int i = 0; i < 6; i++) {
            float s = S[(qr + i) * 97 + k];
            o[i][0] = fmaf(s, v.x, o[i][0]);
            o[i][1] = fmaf(s, v.y, o[i][1]);
            o[i][2] = fmaf(s, v.z, o[i][2]);
            o[i][3] = fmaf(s, v.w, o[i][3]);
        }
    }
    float* ob = Og + base;
#pragma unroll
    for (int i = 0; i < 6; i++) {
        int r = qr + i;
        float inv = 1.0f / rowred[r];
        float4 ov;
        ov.x = o[i][0] * inv; ov.y = o[i][1] * inv;
        ov.z = o[i][2] * inv; ov.w = o[i][3] * inv;
        *(float4*)(ob + (size_t)r * 512 + tx * 4) = ov;
    }
}

// ---------------------------------------------------------------------------
// BN constants precompute (keeps rsqrt off the hot path)
// ---------------------------------------------------------------------------
__global__ void bnprep(const float* __restrict__ g, const float* __restrict__ b,
                       const float* __restrict__ m, const float* __restrict__ v) {
    int c = blockIdx.x * 256 + threadIdx.x;
    if (c < 512) {
        float sc = g[c] * rsqrtf(v[c] + 1e-5f);
        g_bnscale[c] = sc;
        g_bnbias[c]  = b[c] - m[c] * sc;
    }
}

// depthwise 3x3 SAME + BN(eval), NCHW -> NCHW
__global__ void dwconv_bn(const float* __restrict__ x, const float* __restrict__ wd,
                          float* __restrict__ o) {
    int idx = blockIdx.x * 256 + threadIdx.x;  // exact grid, no bounds check
    int w = idx % 96;
    int t = idx / 96;
    int h = t % 96;
    int bc = t / 96;           // b*512 + c
    int c = bc & 511;
    const float* wt = wd + c * 9;
    const float* xp = x + (size_t)bc * 9216;
    float s = 0.f;
#pragma unroll
    for (int kh = -1; kh <= 1; kh++) {
        int hh = h + kh;
        if (hh < 0 || hh >= 96) continue;
#pragma unroll
        for (int kw = -1; kw <= 1; kw++) {
            int ww = w + kw;
            if (ww < 0 || ww >= 96) continue;
            s = fmaf(xp[hh * 96 + ww], wt[(kh + 1) * 3 + (kw + 1)], s);
        }
    }
    o[idx] = fmaf(s, g_bnscale[c], g_bnbias[c]);
}

// ---------------------------------------------------------------------------
// 1x1 conv GEMM per batch: Out[o, p] = clip(pw[o,:] @ tmp[:, p], 0, 6) + cr[o, p]
// A = pw [512,512] row-major (M,K); B = tmp NCHW slice [512, 9216] (K,N)
// BM=64 BN=128 BK=16, 256 threads, 8x4 register tile. Coalesced stores.
// ---------------------------------------------------------------------------
__global__ __launch_bounds__(256) void gemm_conv(
    const float* __restrict__ Apw, const float* __restrict__ Bt,
    const float* __restrict__ CR, float* __restrict__ Out)
{
    __shared__ float As[16][72];
    __shared__ float Bs[16][132];
    int bat = blockIdx.z;
    size_t boff = (size_t)bat * 512 * 9216;
    const float* B = Bt + boff;
    int n0 = blockIdx.x * 128;
    int m0 = blockIdx.y * 64;
    int tid = threadIdx.x;
    int tx = tid & 31, ty = tid >> 5;
    float acc[8][4];
#pragma unroll
    for (int i = 0; i < 8; i++)
#pragma unroll
        for (int j = 0; j < 4; j++) acc[i][j] = 0.f;

    for (int k0 = 0; k0 < 512; k0 += 16) {
        {
            int row = tid >> 2, c4 = (tid & 3) * 4;
            float4 v = *(const float4*)(Apw + (size_t)(m0 + row) * 512 + k0 + c4);
            As[c4 + 0][row] = v.x; As[c4 + 1][row] = v.y;
            As[c4 + 2][row] = v.z; As[c4 + 3][row] = v.w;
        }
#pragma unroll
        for (int r = 0; r < 2; r++) {
            int id = tid * 2 + r;
            int krow = id >> 5, cc = (id & 31) * 4;
            float4 v = *(const float4*)(B + (size_t)(k0 + krow) * 9216 + n0 + cc);
            *(float4*)&Bs[krow][cc] = v;
        }
        __syncthreads();
#pragma unroll
        for (int kk = 0; kk < 16; kk++) {
            float4 a0 = *(const float4*)&As[kk][ty * 8];
            float4 a1 = *(const float4*)&As[kk][ty * 8 + 4];
            float4 b  = *(const float4*)&Bs[kk][tx * 4];
            float am[8] = {a0.x, a0.y, a0.z, a0.w, a1.x, a1.y, a1.z, a1.w};
            float bn[4] = {b.x, b.y, b.z, b.w};
#pragma unroll
            for (int i = 0; i < 8; i++)
#pragma unroll
                for (int j = 0; j < 4; j++)
                    acc[i][j] = fmaf(am[i], bn[j], acc[i][j]);
        }
        __syncthreads();
    }
    int nb = n0 + tx * 4;
#pragma unroll
    for (int i = 0; i < 8; i++) {
        int m = m0 + ty * 8 + i;
        size_t off = boff + (size_t)m * 9216 + nb;
        float4 cr = *(const float4*)(CR + off);
        float4 o;
        o.x = fminf(fmaxf(acc[i][0], 0.f), 6.f) + cr.x;
        o.y = fminf(fmaxf(acc[i][1], 0.f), 6.f) + cr.y;
        o.z = fminf(fmaxf(acc[i][2], 0.f), 6.f) + cr.z;
        o.w = fminf(fmaxf(acc[i][3], 0.f), 6.f) + cr.w;
        *(float4*)(Out + off) = o;
    }
}

// ---------------------------------------------------------------------------
// Host launch
// ---------------------------------------------------------------------------
extern "C" void kernel_launch(void* const* d_in, const int* in_sizes, int n_in,
                              void* d_out, int out_size) {
    const float* x   = (const float*)d_in[0];
    const float* Wk  = (const float*)d_in[1];
    const float* Wv  = (const float*)d_in[2];
    const float* Wo  = (const float*)d_in[3];
    const float* cWq = (const float*)d_in[4];
    const float* cbq = (const float*)d_in[5];
    const float* cWv = (const float*)d_in[6];
    const float* cWo = (const float*)d_in[7];
    const float* dww = (const float*)d_in[8];
    const float* bng = (const float*)d_in[9];
    const float* bnb = (const float*)d_in[10];
    const float* bnm = (const float*)d_in[11];
    const float* bnv = (const float*)d_in[12];
    const float* pww = (const float*)d_in[13];
    float* out = (float*)d_out;

    float* bufs = nullptr;
    cudaGetSymbolAddress((void**)&bufs, g_bufs);
    float* b0 = bufs + (size_t)0 * TOTE;
    float* b1 = bufs + (size_t)1 * TOTE;
    float* b2 = bufs + (size_t)2 * TOTE;
    float* b3 = bufs + (size_t)3 * TOTE;
    float* b4 = bufs + (size_t)4 * TOTE;

    const int ATTN_SMEM = (2 * 96 * 65 + 96 * 68 + 96 * 97) * 4;  // 113280
    cudaFuncSetAttribute(attn_kernel, cudaFuncAttributeMaxDynamicSharedMemorySize, ATTN_SMEM);

    dim3 tb(32, 8);
    dim3 tg(3, 16, 768);
    dim3 gg(8, 576);

    // vqk = img2seq(x)
    img2seq<<<tg, tb>>>(x, b0);
    // k = vqk @ Wk^T + vqk ; v = vqk @ Wv^T ; kv = vqk @ cWv^T
    gemm_nt512<<<gg, 256>>>(b0, Wk, b0, nullptr, b1, 1);
    gemm_nt512<<<gg, 256>>>(b0, Wv, nullptr, nullptr, b2, 0);
    gemm_nt512<<<gg, 256>>>(b0, cWv, nullptr, nullptr, b3, 0);
    // a1 = attn(vqk, k, v)
    attn_kernel<<<dim3(8, 768), 256, ATTN_SMEM>>>(b0, b1, b2, b4);
    // o_msa = a1 @ Wo^T
    gemm_nt512<<<gg, 256>>>(b4, Wo, nullptr, nullptr, b0, 0);
    // xp = seq2img(o_msa); q_view is xp's flat reinterpretation
    seq2img<<<tg, tb>>>(b0, b1);
    // q2 = q_view @ cWq^T + cbq
    gemm_nt512<<<gg, 256>>>(b1, cWq, nullptr, cbq, b2, 2);
    // a2 = attn(q2, kv, kv)
    attn_kernel<<<dim3(8, 768), 256, ATTN_SMEM>>>(b2, b3, b3, b0);
    // cr_seq = a2 @ cWo^T
    gemm_nt512<<<gg, 256>>>(b0, cWo, nullptr, nullptr, b1, 0);
    // cr_img = seq2img(cr_seq)
    seq2img<<<tg, tb>>>(b1, b2);
    // conv path
    bnprep<<<2, 256>>>(bng, bnb, bnm, bnv);
    dwconv_bn<<<147456, 256>>>(x, dww, b0);
    // out = clip(pw conv, 0, 6) + cr_img
    gemm_conv<<<dim3(72, 8, 8), 256>>>(pww, b0, b2, out);
}

// round 2
// speedup vs baseline: 2.4228x; 2.4228x over previous
#include <cuda_runtime.h>
#include <math.h>

// ---------------------------------------------------------------------------
// Problem constants: B=8, C=512, H=W=96, heads=8, dh=64
// seq layout: [768, 96, 512]  (n = b*96 + w, t = h, channel c)
// ---------------------------------------------------------------------------
#define TOTE 37748736  // 768*96*512 == 8*512*96*96

__device__ float g_bufs[5][TOTE];
__device__ float g_bnscale[512];
__device__ float g_bnbias[512];

__device__ __forceinline__ unsigned tf32_rna(float x) {
    unsigned r;
    asm("cvt.rna.tf32.f32 %0, %1;" : "=r"(r) : "f"(x));
    return r;
}

// Fast exp via degree-6 poly on 2^f (FMA-only, avoids MUFU bottleneck).
__device__ __forceinline__ float fast_exp(float x) {
    x = fmaxf(x, -87.0f);
    float t = x * 1.44269504088896f;
    float fi = floorf(t);
    float f = t - fi;
    float p = 1.54035304e-4f;
    p = fmaf(p, f, 1.33335581e-3f);
    p = fmaf(p, f, 9.61812910e-3f);
    p = fmaf(p, f, 5.55041087e-2f);
    p = fmaf(p, f, 2.40226507e-1f);
    p = fmaf(p, f, 6.93147181e-1f);
    p = fmaf(p, f, 1.0f);
    return p * __int_as_float(((int)fi + 127) << 23);
}

#define MMA_TF32(c0,c1,c2,c3,a0,a1,a2,a3,b0,b1) \
    asm volatile("mma.sync.aligned.m16n8k8.row.col.f32.tf32.tf32.f32 " \
                 "{%0,%1,%2,%3},{%4,%5,%6,%7},{%8,%9},{%0,%1,%2,%3};" \
                 : "+f"(c0),"+f"(c1),"+f"(c2),"+f"(c3) \
                 : "r"(a0),"r"(a1),"r"(a2),"r"(a3),"r"(b0),"r"(b1))

#define LDSM_X4(r0,r1,r2,r3,addr) \
    asm volatile("ldmatrix.sync.aligned.m8n8.x4.shared.b16 {%0,%1,%2,%3}, [%4];" \
                 : "=r"(r0),"=r"(r1),"=r"(r2),"=r"(r3) : "r"(addr))

// ---------------------------------------------------------------------------
// Layout transposes: per (b,h) plane, transpose (c <-> w), 32x32 smem tiles
// ---------------------------------------------------------------------------
__global__ void img2seq(const float* __restrict__ img, float* __restrict__ seq) {
    __shared__ float tile[32][33];
    int bh = blockIdx.z;
    int b = bh / 96, h = bh % 96;
    int c0 = blockIdx.y * 32, w0 = blockIdx.x * 32;
    int tx = threadIdx.x, ty = threadIdx.y;
#pragma unroll
    for (int i = 0; i < 4; i++) {
        int c = c0 + ty + i * 8;
        tile[ty + i * 8][tx] = img[(((size_t)b * 512 + c) * 96 + h) * 96 + w0 + tx];
    }
    __syncthreads();
#pragma unroll
    for (int i = 0; i < 4; i++) {
        int w = w0 + ty + i * 8;
        seq[(((size_t)(b * 96 + w)) * 96 + h) * 512 + c0 + tx] = tile[tx][ty + i * 8];
    }
}

__global__ void seq2img(const float* __restrict__ seq, float* __restrict__ img) {
    __shared__ float tile[32][33];
    int bh = blockIdx.z;
    int b = bh / 96, h = bh % 96;
    int c0 = blockIdx.y * 32, w0 = blockIdx.x * 32;
    int tx = threadIdx.x, ty = threadIdx.y;
#pragma unroll
    for (int i = 0; i < 4; i++) {
        int w = w0 + ty + i * 8;
        tile[ty + i * 8][tx] = seq[(((size_t)(b * 96 + w)) * 96 + h) * 512 + c0 + tx];
    }
    __syncthreads();
#pragma unroll
    for (int i = 0; i < 4; i++) {
        int c = c0 + ty + i * 8;
        img[(((size_t)b * 512 + c) * 96 + h) * 96 + w0 + tx] = tile[tx][ty + i * 8];
    }
}

// ---------------------------------------------------------------------------
// TF32 tensor-core GEMM: C[M,512] = A[M,512] @ W[512,512]^T  (+A | +bias)
// Block tile 128x128x32, 8 warps (2m x 4n), each warp 64x32 via m16n8k8.
// mode 0: plain; 1: +Add[m,n]; 2: +bias[n]
// ---------------------------------------------------------------------------
__global__ __launch_bounds__(256, 2) void gemm_nt512_tf32(
    const float* __restrict__ A, const float* __restrict__ W,
    const float* __restrict__ Add, const float* __restrict__ bias,
    float* __restrict__ Cout, int mode)
{
    __shared__ float As[128 * 36];   // [m][k], pitch 36
    __shared__ float Ws[128 * 36];   // [n][k], pitch 36
    int m0 = blockIdx.y * 128;
    int n0 = blockIdx.x * 128;
    int tid = threadIdx.x;
    int w = tid >> 5, l = tid & 31;
    int g = l >> 2, t = l & 3;
    int wm = (w & 1) * 64, wn = (w >> 1) * 32;

    // global load indices: 8 float4 chunks per 32-wide row, 32 rows per pass
    int lc = (tid & 7) * 4;
    int lr = tid >> 3;

    // ldmatrix address components
    int p = l & 7, sel = l >> 3;
    int a_row = wm + p + (sel & 1) * 8;
    int a_col = (sel >> 1) * 4;
    unsigned as_base = (unsigned)__cvta_generic_to_shared(As) + (a_row * 36 + a_col) * 4;

    float c[4][4][4];
#pragma unroll
    for (int mi = 0; mi < 4; mi++)
#pragma unroll
        for (int ni = 0; ni < 4; ni++)
#pragma unroll
            for (int r = 0; r < 4; r++) c[mi][ni][r] = 0.f;

    for (int k0 = 0; k0 < 512; k0 += 32) {
#pragma unroll
        for (int i = 0; i < 4; i++) {
            int row = lr + i * 32;
            float4 va = *(const float4*)(A + (size_t)(m0 + row) * 512 + k0 + lc);
            float4 vw = *(const float4*)(W + (size_t)(n0 + row) * 512 + k0 + lc);
            uint4 ua, uw;
            ua.x = tf32_rna(va.x); ua.y = tf32_rna(va.y);
            ua.z = tf32_rna(va.z); ua.w = tf32_rna(va.w);
            uw.x = tf32_rna(vw.x); uw.y = tf32_rna(vw.y);
            uw.z = tf32_rna(vw.z); uw.w = tf32_rna(vw.w);
            *(uint4*)&As[row * 36 + lc] = ua;
            *(uint4*)&Ws[row * 36 + lc] = uw;
        }
        __syncthreads();
#pragma unroll
        for (int ks = 0; ks < 4; ks++) {
            unsigned a[4][4];
#pragma unroll
            for (int mi = 0; mi < 4; mi++) {
                unsigned addr = as_base + (mi * 16 * 36 + ks * 8) * 4;
                LDSM_X4(a[mi][0], a[mi][1], a[mi][2], a[mi][3], addr);
            }
            unsigned b[4][2];
#pragma unroll
            for (int ni = 0; ni < 4; ni++) {
                int nrow = wn + ni * 8 + g;
                b[ni][0] = __float_as_uint(Ws[nrow * 36 + ks * 8 + t]);
                b[ni][1] = __float_as_uint(Ws[nrow * 36 + ks * 8 + t + 4]);
            }
#pragma unroll
            for (int mi = 0; mi < 4; mi++)
#pragma unroll
                for (int ni = 0; ni < 4; ni++)
                    MMA_TF32(c[mi][ni][0], c[mi][ni][1], c[mi][ni][2], c[mi][ni][3],
                             a[mi][0], a[mi][1], a[mi][2], a[mi][3],
                             b[ni][0], b[ni][1]);
        }
        __syncthreads();
    }

#pragma unroll
    for (int mi = 0; mi < 4; mi++) {
#pragma unroll
        for (int ni = 0; ni < 4; ni++) {
            int m = m0 + wm + mi * 16 + g;
            int n = n0 + wn + ni * 8 + 2 * t;
            float v00 = c[mi][ni][0], v01 = c[mi][ni][1];
            float v10 = c[mi][ni][2], v11 = c[mi][ni][3];
            if (mode == 1) {
                float2 a0 = *(const float2*)(Add + (size_t)m * 512 + n);
                float2 a1 = *(const float2*)(Add + (size_t)(m + 8) * 512 + n);
                v00 += a0.x; v01 += a0.y; v10 += a1.x; v11 += a1.y;
            } else if (mode == 2) {
                float2 bb = *(const float2*)(bias + n);
                v00 += bb.x; v01 += bb.y; v10 += bb.x; v11 += bb.y;
            }
            float2 o0 = {v00, v01}, o1 = {v10, v11};
            *(float2*)(Cout + (size_t)m * 512 + n) = o0;
            *(float2*)(Cout + (size_t)(m + 8) * 512 + n) = o1;
        }
    }
}

// ---------------------------------------------------------------------------
// Attention: one block per (n, head). T=96, dh=64. fp32, fast_exp softmax.
// ---------------------------------------------------------------------------
__global__ __launch_bounds__(256) void attn_kernel(
    const float* __restrict__ Qg, const float* __restrict__ Kg,
    const float* __restrict__ Vg, float* __restrict__ Og)
{
    extern __shared__ float sm[];
    float* Qs = sm;
    float* Ks = sm + 96 * 65;
    float* Vs = sm + 2 * 96 * 65;
    float* S  = sm + 2 * 96 * 65 + 96 * 68;
    __shared__ float rowred[96];
    __shared__ float part[96][2];

    int hd = blockIdx.x, n = blockIdx.y;
    size_t base = (size_t)n * 96 * 512 + hd * 64;
    const float* qb = Qg + base;
    const float* kb = Kg + base;
    const float* vb = Vg + base;
    int tid = threadIdx.x;

    for (int i = tid; i < 96 * 16; i += 256) {
        int r = i >> 4, cc = (i & 15) * 4;
        float4 q = *(const float4*)(qb + (size_t)r * 512 + cc);
        float4 k = *(const float4*)(kb + (size_t)r * 512 + cc);
        float4 v = *(const float4*)(vb + (size_t)r * 512 + cc);
        Qs[r * 65 + cc] = q.x; Qs[r * 65 + cc + 1] = q.y; Qs[r * 65 + cc + 2] = q.z; Qs[r * 65 + cc + 3] = q.w;
        Ks[r * 65 + cc] = k.x; Ks[r * 65 + cc + 1] = k.y; Ks[r * 65 + cc + 2] = k.z; Ks[r * 65 + cc + 3] = k.w;
        Vs[r * 68 + cc] = v.x; Vs[r * 68 + cc + 1] = v.y; Vs[r * 68 + cc + 2] = v.z; Vs[r * 68 + cc + 3] = v.w;
    }
    __syncthreads();

    int tx = tid & 15, ty = tid >> 4;
    int qr = ty * 6, kr = tx * 6;
    {
        float acc[6][6];
#pragma unroll
        for (int i = 0; i < 6; i++)
#pragma unroll
            for (int j = 0; j < 6; j++) acc[i][j] = 0.f;
        for (int k = 0; k < 64; k++) {
            float qv[6], kv[6];
#pragma unroll
            for (int i = 0; i < 6; i++) qv[i] = Qs[(qr + i) * 65 + k];
#pragma unroll
            for (int j = 0; j < 6; j++) kv[j] = Ks[(kr + j) * 65 + k];
#pragma unroll
            for (int i = 0; i < 6; i++)
#pragma unroll
                for (int j = 0; j < 6; j++)
                    acc[i][j] = fmaf(qv[i], kv[j], acc[i][j]);
        }
#pragma unroll
        for (int i = 0; i < 6; i++)
#pragma unroll
            for (int j = 0; j < 6; j++)
                S[(qr + i) * 97 + kr + j] = acc[i][j] * 0.125f;
    }
    __syncthreads();

    if (tid < 192) {
        int r = tid >> 1, hf = (tid & 1) * 48;
        float m = -1e30f;
        for (int cc = 0; cc < 48; cc++) m = fmaxf(m, S[r * 97 + hf + cc]);
        part[r][tid & 1] = m;
    }
    __syncthreads();
    if (tid < 96) rowred[tid] = fmaxf(part[tid][0], part[tid][1]);
    __syncthreads();
    for (int i = tid; i < 96 * 96; i += 256) {
        int r = i / 96, cc = i - r * 96;
        S[r * 97 + cc] = fast_exp(S[r * 97 + cc] - rowred[r]);
    }
    __syncthreads();
    if (tid < 192) {
        int r = tid >> 1, hf = (tid & 1) * 48;
        float s = 0.f;
        for (int cc = 0; cc < 48; cc++) s += S[r * 97 + hf + cc];
        part[r][tid & 1] = s;
    }
    __syncthreads();
    if (tid < 96) rowred[tid] = part[tid][0] + part[tid][1];
    __syncthreads();

    float o[6][4];
#pragma unroll
    for (int i = 0; i < 6; i++)
#pragma unroll
        for (int j = 0; j < 4; j++) o[i][j] = 0.f;
    for (int k = 0; k < 96; k++) {
        float4 v = *(const float4*)&Vs[k * 68 + tx * 4];
#pragma unroll
        for (int i = 0; i < 6; i++) {
            float s = S[(qr + i) * 97 + k];
            o[i][0] = fmaf(s, v.x, o[i][0]);
            o[i][1] = fmaf(s, v.y, o[i][1]);
            o[i][2] = fmaf(s, v.z, o[i][2]);
            o[i][3] = fmaf(s, v.w, o[i][3]);
        }
    }
    float* ob = Og + base;
#pragma unroll
    for (int i = 0; i < 6; i++) {
        int r = qr + i;
        float inv = 1.0f / rowred[r];
        float4 ov;
        ov.x = o[i][0] * inv; ov.y = o[i][1] * inv;
        ov.z = o[i][2] * inv; ov.w = o[i][3] * inv;
        *(float4*)(ob + (size_t)r * 512 + tx * 4) = ov;
    }
}

// ---------------------------------------------------------------------------
__global__ void bnprep(const float* __restrict__ g, const float* __restrict__ b,
                       const float* __restrict__ m, const float* __restrict__ v) {
    int c = blockIdx.x * 256 + threadIdx.x;
    if (c < 512) {
        float sc = g[c] * rsqrtf(v[c] + 1e-5f);
        g_bnscale[c] = sc;
        g_bnbias[c]  = b[c] - m[c] * sc;
    }
}

__global__ void dwconv_bn(const float* __restrict__ x, const float* __restrict__ wd,
                          float* __restrict__ o) {
    int idx = blockIdx.x * 256 + threadIdx.x;
    int w = idx % 96;
    int t = idx / 96;
    int h = t % 96;
    int bc = t / 96;
    int c = bc & 511;
    const float* wt = wd + c * 9;
    const float* xp = x + (size_t)bc * 9216;
    float s = 0.f;
#pragma unroll
    for (int kh = -1; kh <= 1; kh++) {
        int hh = h + kh;
        if (hh < 0 || hh >= 96) continue;
#pragma unroll
        for (int kw = -1; kw <= 1; kw++) {
            int ww = w + kw;
            if (ww < 0 || ww >= 96) continue;
            s = fmaf(xp[hh * 96 + ww], wt[(kh + 1) * 3 + (kw + 1)], s);
        }
    }
    o[idx] = fmaf(s, g_bnscale[c], g_bnbias[c]);
}

// ---------------------------------------------------------------------------
// TF32 1x1-conv GEMM per batch: Out = clip(pw @ tmp, 0, 6) + CR
// A = pw [512,512] (m,k) ; B = tmp slice [512,9216] (k,n)
// Block 128x128x32, 8 warps. Bs stored [k][n] pitch 136.
// ---------------------------------------------------------------------------
__global__ __launch_bounds__(256, 2) void gemm_conv_tf32(
    const float* __restrict__ Apw, const float* __restrict__ Bt,
    const float* __restrict__ CR, float* __restrict__ Out)
{
    __shared__ float As[128 * 36];   // [m][k]
    __shared__ float Bs[32 * 136];   // [k][n]
    int bat = blockIdx.z;
    size_t boff = (size_t)bat * 512 * 9216;
    const float* Bg = Bt + boff;
    int n0 = blockIdx.x * 128;
    int m0 = blockIdx.y * 128;
    int tid = threadIdx.x;
    int w = tid >> 5, l = tid & 31;
    int g = l >> 2, t = l & 3;
    int wm = (w & 1) * 64, wn = (w >> 1) * 32;

    int lcA = (tid & 7) * 4;
    int lrA = tid >> 3;
    int lcB = (tid & 31) * 4;
    int lrB = tid >> 5;

    int p = l & 7, sel = l >> 3;
    int a_row = wm + p + (sel & 1) * 8;
    int a_col = (sel >> 1) * 4;
    unsigned as_base = (unsigned)__cvta_generic_to_shared(As) + (a_row * 36 + a_col) * 4;

    float c[4][4][4];
#pragma unroll
    for (int mi = 0; mi < 4; mi++)
#pragma unroll
        for (int ni = 0; ni < 4; ni++)
#pragma unroll
            for (int r = 0; r < 4; r++) c[mi][ni][r] = 0.f;

    for (int k0 = 0; k0 < 512; k0 += 32) {
#pragma unroll
        for (int i = 0; i < 4; i++) {
            int rowA = lrA + i * 32;
            float4 va = *(const float4*)(Apw + (size_t)(m0 + rowA) * 512 + k0 + lcA);
            uint4 ua;
            ua.x = tf32_rna(va.x); ua.y = tf32_rna(va.y);
            ua.z = tf32_rna(va.z); ua.w = tf32_rna(va.w);
            *(uint4*)&As[rowA * 36 + lcA] = ua;

            int rowB = lrB + i * 8;
            float4 vb = *(const float4*)(Bg + (size_t)(k0 + rowB) * 9216 + n0 + lcB);
            uint4 ub;
            ub.x = tf32_rna(vb.x); ub.y = tf32_rna(vb.y);
            ub.z = tf32_rna(vb.z); ub.w = tf32_rna(vb.w);
            *(uint4*)&Bs[rowB * 136 + lcB] = ub;
        }
        __syncthreads();
#pragma unroll
        for (int ks = 0; ks < 4; ks++) {
            unsigned a[4][4];
#pragma unroll
            for (int mi = 0; mi < 4; mi++) {
                unsigned addr = as_base + (mi * 16 * 36 + ks * 8) * 4;
                LDSM_X4(a[mi][0], a[mi][1], a[mi][2], a[mi][3], addr);
            }
            unsigned b[4][2];
#pragma unroll
            for (int ni = 0; ni < 4; ni++) {
                int ncol = wn + ni * 8 + g;
                b[ni][0] = __float_as_uint(Bs[(ks * 8 + t) * 136 + ncol]);
                b[ni][1] = __float_as_uint(Bs[(ks * 8 + t + 4) * 136 + ncol]);
            }
#pragma unroll
            for (int mi = 0; mi < 4; mi++)
#pragma unroll
                for (int ni = 0; ni < 4; ni++)
                    MMA_TF32(c[mi][ni][0], c[mi][ni][1], c[mi][ni][2], c[mi][ni][3],
                             a[mi][0], a[mi][1], a[mi][2], a[mi][3],
                             b[ni][0], b[ni][1]);
        }
        __syncthreads();
    }

#pragma unroll
    for (int mi = 0; mi < 4; mi++) {
#pragma unroll
        for (int ni = 0; ni < 4; ni++) {
            int m = m0 + wm + mi * 16 + g;
            int n = n0 + wn + ni * 8 + 2 * t;
            size_t off0 = boff + (size_t)m * 9216 + n;
            size_t off1 = boff + (size_t)(m + 8) * 9216 + n;
            float2 cr0 = *(const float2*)(CR + off0);
            float2 cr1 = *(const float2*)(CR + off1);
            float2 o0, o1;
            o0.x = fminf(fmaxf(c[mi][ni][0], 0.f), 6.f) + cr0.x;
            o0.y = fminf(fmaxf(c[mi][ni][1], 0.f), 6.f) + cr0.y;
            o1.x = fminf(fmaxf(c[mi][ni][2], 0.f), 6.f) + cr1.x;
            o1.y = fminf(fmaxf(c[mi][ni][3], 0.f), 6.f) + cr1.y;
            *(float2*)(Out + off0) = o0;
            *(float2*)(Out + off1) = o1;
        }
    }
}

// ---------------------------------------------------------------------------
// Host launch
// ---------------------------------------------------------------------------
extern "C" void kernel_launch(void* const* d_in, const int* in_sizes, int n_in,
                              void* d_out, int out_size) {
    const float* x   = (const float*)d_in[0];
    const float* Wk  = (const float*)d_in[1];
    const float* Wv  = (const float*)d_in[2];
    const float* Wo  = (const float*)d_in[3];
    const float* cWq = (const float*)d_in[4];
    const float* cbq = (const float*)d_in[5];
    const float* cWv = (const float*)d_in[6];
    const float* cWo = (const float*)d_in[7];
    const float* dww = (const float*)d_in[8];
    const float* bng = (const float*)d_in[9];
    const float* bnb = (const float*)d_in[10];
    const float* bnm = (const float*)d_in[11];
    const float* bnv = (const float*)d_in[12];
    const float* pww = (const float*)d_in[13];
    float* out = (float*)d_out;

    float* bufs = nullptr;
    cudaGetSymbolAddress((void**)&bufs, g_bufs);
    float* b0 = bufs + (size_t)0 * TOTE;
    float* b1 = bufs + (size_t)1 * TOTE;
    float* b2 = bufs + (size_t)2 * TOTE;
    float* b3 = bufs + (size_t)3 * TOTE;
    float* b4 = bufs + (size_t)4 * TOTE;

    const int ATTN_SMEM = (2 * 96 * 65 + 96 * 68 + 96 * 97) * 4;
    cudaFuncSetAttribute(attn_kernel, cudaFuncAttributeMaxDynamicSharedMemorySize, ATTN_SMEM);

    dim3 tb(32, 8);
    dim3 tg(3, 16, 768);
    dim3 gg(4, 576);   // tf32 gemm: N/128=4, M/128=576

    img2seq<<<tg, tb>>>(x, b0);
    gemm_nt512_tf32<<<gg, 256>>>(b0, Wk, b0, nullptr, b1, 1);
    gemm_nt512_tf32<<<gg, 256>>>(b0, Wv, nullptr, nullptr, b2, 0);
    gemm_nt512_tf32<<<gg, 256>>>(b0, cWv, nullptr, nullptr, b3, 0);
    attn_kernel<<<dim3(8, 768), 256, ATTN_SMEM>>>(b0, b1, b2, b4);
    gemm_nt512_tf32<<<gg, 256>>>(b4, Wo, nullptr, nullptr, b0, 0);
    seq2img<<<tg, tb>>>(b0, b1);
    gemm_nt512_tf32<<<gg, 256>>>(b1, cWq, nullptr, cbq, b2, 2);
    attn_kernel<<<dim3(8, 768), 256, ATTN_SMEM>>>(b2, b3, b3, b0);
    gemm_nt512_tf32<<<gg, 256>>>(b0, cWo, nullptr, nullptr, b1, 0);
    seq2img<<<tg, tb>>>(b1, b2);
    bnprep<<<2, 256>>>(bng, bnb, bnm, bnv);
    dwconv_bn<<<147456, 256>>>(x, dww, b0);
    gemm_conv_tf32<<<dim3(72, 4, 8), 256>>>(pww, b0, b2, out);
}

// round 3
// speedup vs baseline: 2.9839x; 1.2316x over previous
#include <cuda_runtime.h>
#include <math.h>

// ---------------------------------------------------------------------------
// Problem constants: B=8, C=512, H=W=96, heads=8, dh=64
// seq layout: [768, 96, 512]  (n = b*96 + w, t = h, channel c)
// ---------------------------------------------------------------------------
#define TOTE 37748736  // 768*96*512

__device__ float g_bufs[5][TOTE];
__device__ float g_w[7 * 262144];   // tf32-rounded weights
__device__ float g_bnscale[512];
__device__ float g_bnbias[512];

__device__ __forceinline__ unsigned tf32_rna(float x) {
    unsigned r;
    asm("cvt.rna.tf32.f32 %0, %1;" : "=r"(r) : "f"(x));
    return r;
}
__device__ __forceinline__ float tf32f(float x) { return __uint_as_float(tf32_rna(x)); }

__device__ __forceinline__ float fast_exp(float x) {
    x = fmaxf(x, -87.0f);
    float t = x * 1.44269504088896f;
    float fi = floorf(t);
    float f = t - fi;
    float p = 1.54035304e-4f;
    p = fmaf(p, f, 1.33335581e-3f);
    p = fmaf(p, f, 9.61812910e-3f);
    p = fmaf(p, f, 5.55041087e-2f);
    p = fmaf(p, f, 2.40226507e-1f);
    p = fmaf(p, f, 6.93147181e-1f);
    p = fmaf(p, f, 1.0f);
    return p * __int_as_float(((int)fi + 127) << 23);
}

#define MMA_TF32(c0,c1,c2,c3,a0,a1,a2,a3,b0,b1) \
    asm volatile("mma.sync.aligned.m16n8k8.row.col.f32.tf32.tf32.f32 " \
                 "{%0,%1,%2,%3},{%4,%5,%6,%7},{%8,%9},{%0,%1,%2,%3};" \
                 : "+f"(c0),"+f"(c1),"+f"(c2),"+f"(c3) \
                 : "r"(a0),"r"(a1),"r"(a2),"r"(a3),"r"(b0),"r"(b1))

#define LDSM_X4(r0,r1,r2,r3,addr) \
    asm volatile("ldmatrix.sync.aligned.m8n8.x4.shared.b16 {%0,%1,%2,%3}, [%4];" \
                 : "=r"(r0),"=r"(r1),"=r"(r2),"=r"(r3) : "r"(addr))

#define CP16(dst, src) \
    asm volatile("cp.async.cg.shared.global [%0], [%1], 16;" :: "r"(dst), "l"(src))
#define CP_COMMIT() asm volatile("cp.async.commit_group;")
#define CP_WAIT0()  asm volatile("cp.async.wait_group 0;")

// ---------------------------------------------------------------------------
// Weight prep: RNA-round 7 [512x512] matrices into g_w
// ---------------------------------------------------------------------------
__global__ void wprep(const float* __restrict__ a0, const float* __restrict__ a1,
                      const float* __restrict__ a2, const float* __restrict__ a3,
                      const float* __restrict__ a4, const float* __restrict__ a5,
                      const float* __restrict__ a6) {
    int i = blockIdx.x * 256 + threadIdx.x;      // 458752 float4 total
    int mat = i >> 16;
    int off = (i & 65535) * 4;
    const float* s;
    switch (mat) {
        case 0: s = a0; break; case 1: s = a1; break; case 2: s = a2; break;
        case 3: s = a3; break; case 4: s = a4; break; case 5: s = a5; break;
        default: s = a6; break;
    }
    float4 v = *(const float4*)(s + off);
    v.x = tf32f(v.x); v.y = tf32f(v.y); v.z = tf32f(v.z); v.w = tf32f(v.w);
    *(float4*)(g_w + (size_t)mat * 262144 + off) = v;
}

// ---------------------------------------------------------------------------
// Layout transposes (c <-> w per (b,h) plane), RNA-round per flag
// ---------------------------------------------------------------------------
__global__ void img2seq(const float* __restrict__ img, float* __restrict__ seq) {
    __shared__ float tile[32][33];
    int bh = blockIdx.z;
    int b = bh / 96, h = bh % 96;
    int c0 = blockIdx.y * 32, w0 = blockIdx.x * 32;
    int tx = threadIdx.x, ty = threadIdx.y;
#pragma unroll
    for (int i = 0; i < 4; i++) {
        int c = c0 + ty + i * 8;
        tile[ty + i * 8][tx] = img[(((size_t)b * 512 + c) * 96 + h) * 96 + w0 + tx];
    }
    __syncthreads();
#pragma unroll
    for (int i = 0; i < 4; i++) {
        int w = w0 + ty + i * 8;
        seq[(((size_t)(b * 96 + w)) * 96 + h) * 512 + c0 + tx] = tf32f(tile[tx][ty + i * 8]);
    }
}

template<bool ROUND>
__global__ void seq2img(const float* __restrict__ seq, float* __restrict__ img) {
    __shared__ float tile[32][33];
    int bh = blockIdx.z;
    int b = bh / 96, h = bh % 96;
    int c0 = blockIdx.y * 32, w0 = blockIdx.x * 32;
    int tx = threadIdx.x, ty = threadIdx.y;
#pragma unroll
    for (int i = 0; i < 4; i++) {
        int w = w0 + ty + i * 8;
        tile[ty + i * 8][tx] = seq[(((size_t)(b * 96 + w)) * 96 + h) * 512 + c0 + tx];
    }
    __syncthreads();
#pragma unroll
    for (int i = 0; i < 4; i++) {
        int c = c0 + ty + i * 8;
        float v = tile[tx][ty + i * 8];
        if (ROUND) v = tf32f(v);
        img[(((size_t)b * 512 + c) * 96 + h) * 96 + w0 + tx] = v;
    }
}

// ---------------------------------------------------------------------------
// TF32 GEMM (inputs pre-rounded): C[M,512] = A @ W^T (+A | +bias)
// 128x128x32 block, 2-stage cp.async pipeline, 8 warps.
// ---------------------------------------------------------------------------
__global__ __launch_bounds__(256, 2) void gemm_nt512_tf32(
    const float* __restrict__ A, const float* __restrict__ W,
    const float* __restrict__ Add, const float* __restrict__ bias,
    float* __restrict__ Cout, int mode)
{
    extern __shared__ float sm[];
    float* As = sm;            // [2][128*36]
    float* Ws = sm + 9216;     // [2][128*36]
    int m0 = blockIdx.y * 128;
    int n0 = blockIdx.x * 128;
    int tid = threadIdx.x;
    int w = tid >> 5, l = tid & 31;
    int g = l >> 2, t = l & 3;
    int wm = (w & 1) * 64, wn = (w >> 1) * 32;
    int lc = (tid & 7) * 4, lr = tid >> 3;

    unsigned sa = (unsigned)__cvta_generic_to_shared(As);
    unsigned sw = (unsigned)__cvta_generic_to_shared(Ws);
    int p = l & 7, sel = l >> 3;
    unsigned a_off = (unsigned)(((wm + p + (sel & 1) * 8) * 36 + (sel >> 1) * 4) * 4);

    float c[4][4][4];
#pragma unroll
    for (int mi = 0; mi < 4; mi++)
#pragma unroll
        for (int ni = 0; ni < 4; ni++)
#pragma unroll
            for (int r = 0; r < 4; r++) c[mi][ni][r] = 0.f;

#define G_LOAD(st, k0) do { \
    _Pragma("unroll") \
    for (int i = 0; i < 4; i++) { \
        int row = lr + i * 32; \
        unsigned da = sa + (unsigned)(((st) * 4608 + row * 36 + lc) * 4); \
        unsigned dw = sw + (unsigned)(((st) * 4608 + row * 36 + lc) * 4); \
        CP16(da, A + (size_t)(m0 + row) * 512 + (k0) + lc); \
        CP16(dw, W + (size_t)(n0 + row) * 512 + (k0) + lc); \
    } \
    CP_COMMIT(); } while (0)

    G_LOAD(0, 0);
#pragma unroll 1
    for (int kt = 0; kt < 16; kt++) {
        int cur = kt & 1;
        CP_WAIT0();
        __syncthreads();
        if (kt < 15) G_LOAD(cur ^ 1, (kt + 1) * 32);
        const float* WsC = Ws + cur * 4608;
        unsigned abase = sa + (unsigned)(cur * 4608 * 4) + a_off;
#pragma unroll
        for (int ks = 0; ks < 4; ks++) {
            unsigned a[4][4];
#pragma unroll
            for (int mi = 0; mi < 4; mi++) {
                unsigned addr = abase + (unsigned)((mi * 16 * 36 + ks * 8) * 4);
                LDSM_X4(a[mi][0], a[mi][1], a[mi][2], a[mi][3], addr);
            }
            unsigned b[4][2];
#pragma unroll
            for (int ni = 0; ni < 4; ni++) {
                int nrow = wn + ni * 8 + g;
                b[ni][0] = __float_as_uint(WsC[nrow * 36 + ks * 8 + t]);
                b[ni][1] = __float_as_uint(WsC[nrow * 36 + ks * 8 + t + 4]);
            }
#pragma unroll
            for (int mi = 0; mi < 4; mi++)
#pragma unroll
                for (int ni = 0; ni < 4; ni++)
                    MMA_TF32(c[mi][ni][0], c[mi][ni][1], c[mi][ni][2], c[mi][ni][3],
                             a[mi][0], a[mi][1], a[mi][2], a[mi][3],
                             b[ni][0], b[ni][1]);
        }
    }
#undef G_LOAD

#pragma unroll
    for (int mi = 0; mi < 4; mi++) {
#pragma unroll
        for (int ni = 0; ni < 4; ni++) {
            int m = m0 + wm + mi * 16 + g;
            int n = n0 + wn + ni * 8 + 2 * t;
            float v00 = c[mi][ni][0], v01 = c[mi][ni][1];
            float v10 = c[mi][ni][2], v11 = c[mi][ni][3];
            if (mode == 1) {
                float2 a0 = *(const float2*)(Add + (size_t)m * 512 + n);
                float2 a1 = *(const float2*)(Add + (size_t)(m + 8) * 512 + n);
                v00 += a0.x; v01 += a0.y; v10 += a1.x; v11 += a1.y;
            } else if (mode == 2) {
                float2 bb = *(const float2*)(bias + n);
                v00 += bb.x; v01 += bb.y; v10 += bb.x; v11 += bb.y;
            }
            float2 o0 = {v00, v01}, o1 = {v10, v11};
            *(float2*)(Cout + (size_t)m * 512 + n) = o0;
            *(float2*)(Cout + (size_t)(m + 8) * 512 + n) = o1;
        }
    }
}

// ---------------------------------------------------------------------------
// Tensor-core attention: one block per (n,head), 192 threads (6 warps).
// Warp w computes q-rows [16w, 16w+16). QK^T and PV via m16n8k8 TF32.
// Softmax in register fragments with quad-lane shfl reductions.
// Output RNA-rounded.
// ---------------------------------------------------------------------------
__global__ __launch_bounds__(192, 2) void attn_tc(
    const float* __restrict__ Qg, const float* __restrict__ Kg,
    const float* __restrict__ Vg, float* __restrict__ Og)
{
    extern __shared__ float sm[];
    float* Qs = sm;              // [96][68]
    float* Ks = sm + 96 * 68;    // [96][68]
    float* Vs = sm + 2 * 96 * 68; // [96][72]
    float* Ps = sm;              // alias over Qs/Ks: [96][100]

    int hd = blockIdx.x, n = blockIdx.y;
    size_t base = (size_t)n * 96 * 512 + hd * 64;
    int tid = threadIdx.x;
    int w = tid >> 5, l = tid & 31;
    int g = l >> 2, t = l & 3;
    int qr = w * 16;

    // Load Q,K,V (96x64 each), RNA-rounding on the way in.
    for (int i = tid; i < 96 * 16; i += 192) {
        int r = i >> 4, cc = (i & 15) * 4;
        float4 q = *(const float4*)(Qg + base + (size_t)r * 512 + cc);
        float4 k = *(const float4*)(Kg + base + (size_t)r * 512 + cc);
        float4 v = *(const float4*)(Vg + base + (size_t)r * 512 + cc);
        Qs[r * 68 + cc + 0] = tf32f(q.x); Qs[r * 68 + cc + 1] = tf32f(q.y);
        Qs[r * 68 + cc + 2] = tf32f(q.z); Qs[r * 68 + cc + 3] = tf32f(q.w);
        Ks[r * 68 + cc + 0] = tf32f(k.x); Ks[r * 68 + cc + 1] = tf32f(k.y);
        Ks[r * 68 + cc + 2] = tf32f(k.z); Ks[r * 68 + cc + 3] = tf32f(k.w);
        Vs[r * 72 + cc + 0] = tf32f(v.x); Vs[r * 72 + cc + 1] = tf32f(v.y);
        Vs[r * 72 + cc + 2] = tf32f(v.z); Vs[r * 72 + cc + 3] = tf32f(v.w);
    }
    __syncthreads();

    // S[16][96] = Q K^T / 8 in fragments c[12][4]
    float c[12][4];
#pragma unroll
    for (int ni = 0; ni < 12; ni++)
#pragma unroll
        for (int r = 0; r < 4; r++) c[ni][r] = 0.f;

#pragma unroll
    for (int k0 = 0; k0 < 64; k0 += 8) {
        unsigned a0 = __float_as_uint(Qs[(qr + g) * 68 + k0 + t]);
        unsigned a1 = __float_as_uint(Qs[(qr + g + 8) * 68 + k0 + t]);
        unsigned a2 = __float_as_uint(Qs[(qr + g) * 68 + k0 + t + 4]);
        unsigned a3 = __float_as_uint(Qs[(qr + g + 8) * 68 + k0 + t + 4]);
#pragma unroll
        for (int ni = 0; ni < 12; ni++) {
            unsigned b0 = __float_as_uint(Ks[(ni * 8 + g) * 68 + k0 + t]);
            unsigned b1 = __float_as_uint(Ks[(ni * 8 + g) * 68 + k0 + t + 4]);
            MMA_TF32(c[ni][0], c[ni][1], c[ni][2], c[ni][3], a0, a1, a2, a3, b0, b1);
        }
    }

    // softmax over rows (qr+g) [c0,c1] and (qr+g+8) [c2,c3]
    float m0 = -1e30f, m1 = -1e30f;
#pragma unroll
    for (int ni = 0; ni < 12; ni++) {
#pragma unroll
        for (int r = 0; r < 4; r++) c[ni][r] *= 0.125f;
        m0 = fmaxf(m0, fmaxf(c[ni][0], c[ni][1]));
        m1 = fmaxf(m1, fmaxf(c[ni][2], c[ni][3]));
    }
    m0 = fmaxf(m0, __shfl_xor_sync(0xffffffff, m0, 1));
    m0 = fmaxf(m0, __shfl_xor_sync(0xffffffff, m0, 2));
    m1 = fmaxf(m1, __shfl_xor_sync(0xffffffff, m1, 1));
    m1 = fmaxf(m1, __shfl_xor_sync(0xffffffff, m1, 2));
    float s0 = 0.f, s1 = 0.f;
#pragma unroll
    for (int ni = 0; ni < 12; ni++) {
        c[ni][0] = fast_exp(c[ni][0] - m0);
        c[ni][1] = fast_exp(c[ni][1] - m0);
        c[ni][2] = fast_exp(c[ni][2] - m1);
        c[ni][3] = fast_exp(c[ni][3] - m1);
        s0 += c[ni][0] + c[ni][1];
        s1 += c[ni][2] + c[ni][3];
    }
    s0 += __shfl_xor_sync(0xffffffff, s0, 1);
    s0 += __shfl_xor_sync(0xffffffff, s0, 2);
    s1 += __shfl_xor_sync(0xffffffff, s1, 1);
    s1 += __shfl_xor_sync(0xffffffff, s1, 2);

    __syncthreads();  // all warps done reading Qs/Ks before Ps overwrite

    // store P (rounded) to smem [96][100]
#pragma unroll
    for (int ni = 0; ni < 12; ni++) {
        float2 p0 = {tf32f(c[ni][0]), tf32f(c[ni][1])};
        float2 p1 = {tf32f(c[ni][2]), tf32f(c[ni][3])};
        *(float2*)&Ps[(qr + g) * 100 + ni * 8 + 2 * t] = p0;
        *(float2*)&Ps[(qr + g + 8) * 100 + ni * 8 + 2 * t] = p1;
    }
    __syncwarp();

    // O[16][64] = P @ V
    float o[8][4];
#pragma unroll
    for (int ni = 0; ni < 8; ni++)
#pragma unroll
        for (int r = 0; r < 4; r++) o[ni][r] = 0.f;
#pragma unroll
    for (int k0 = 0; k0 < 96; k0 += 8) {
        unsigned a0 = __float_as_uint(Ps[(qr + g) * 100 + k0 + t]);
        unsigned a1 = __float_as_uint(Ps[(qr + g + 8) * 100 + k0 + t]);
        unsigned a2 = __float_as_uint(Ps[(qr + g) * 100 + k0 + t + 4]);
        unsigned a3 = __float_as_uint(Ps[(qr + g + 8) * 100 + k0 + t + 4]);
#pragma unroll
        for (int ni = 0; ni < 8; ni++) {
            unsigned b0 = __float_as_uint(Vs[(k0 + t) * 72 + ni * 8 + g]);
            unsigned b1 = __float_as_uint(Vs[(k0 + t + 4) * 72 + ni * 8 + g]);
            MMA_TF32(o[ni][0], o[ni][1], o[ni][2], o[ni][3], a0, a1, a2, a3, b0, b1);
        }
    }

    float inv0 = 1.0f / s0, inv1 = 1.0f / s1;
    float* ob = Og + base;
#pragma unroll
    for (int ni = 0; ni < 8; ni++) {
        float2 v0 = {tf32f(o[ni][0] * inv0), tf32f(o[ni][1] * inv0)};
        float2 v1 = {tf32f(o[ni][2] * inv1), tf32f(o[ni][3] * inv1)};
        *(float2*)(ob + (size_t)(qr + g) * 512 + ni * 8 + 2 * t) = v0;
        *(float2*)(ob + (size_t)(qr + g + 8) * 512 + ni * 8 + 2 * t) = v1;
    }
}

// ---------------------------------------------------------------------------
__global__ void bnprep(const float* __restrict__ g, const float* __restrict__ b,
                       const float* __restrict__ m, const float* __restrict__ v) {
    int c = blockIdx.x * 256 + threadIdx.x;
    if (c < 512) {
        float sc = g[c] * rsqrtf(v[c] + 1e-5f);
        g_bnscale[c] = sc;
        g_bnbias[c]  = b[c] - m[c] * sc;
    }
}

__global__ void dwconv_bn(const float* __restrict__ x, const float* __restrict__ wd,
                          float* __restrict__ o) {
    int idx = blockIdx.x * 256 + threadIdx.x;
    int w = idx % 96;
    int t = idx / 96;
    int h = t % 96;
    int bc = t / 96;
    int c = bc & 511;
    const float* wt = wd + c * 9;
    const float* xp = x + (size_t)bc * 9216;
    float s = 0.f;
#pragma unroll
    for (int kh = -1; kh <= 1; kh++) {
        int hh = h + kh;
        if (hh < 0 || hh >= 96) continue;
#pragma unroll
        for (int kw = -1; kw <= 1; kw++) {
            int ww = w + kw;
            if (ww < 0 || ww >= 96) continue;
            s = fmaf(xp[hh * 96 + ww], wt[(kh + 1) * 3 + (kw + 1)], s);
        }
    }
    o[idx] = tf32f(fmaf(s, g_bnscale[c], g_bnbias[c]));
}

// ---------------------------------------------------------------------------
// TF32 1x1-conv GEMM per batch (inputs pre-rounded), 2-stage cp.async.
// ---------------------------------------------------------------------------
__global__ __launch_bounds__(256, 2) void gemm_conv_tf32(
    const float* __restrict__ Apw, const float* __restrict__ Bt,
    const float* __restrict__ CR, float* __restrict__ Out)
{
    extern __shared__ float sm[];
    float* As = sm;            // [2][128*36]
    float* Bs = sm + 9216;     // [2][32*136]
    int bat = blockIdx.z;
    size_t boff = (size_t)bat * 512 * 9216;
    const float* Bg = Bt + boff;
    int n0 = blockIdx.x * 128;
    int m0 = blockIdx.y * 128;
    int tid = threadIdx.x;
    int w = tid >> 5, l = tid & 31;
    int g = l >> 2, t = l & 3;
    int wm = (w & 1) * 64, wn = (w >> 1) * 32;

    int lcA = (tid & 7) * 4, lrA = tid >> 3;
    int lcB = (tid & 31) * 4, lrB = tid >> 5;

    unsigned sa = (unsigned)__cvta_generic_to_shared(As);
    unsigned sb = (unsigned)__cvta_generic_to_shared(Bs);
    int p = l & 7, sel = l >> 3;
    unsigned a_off = (unsigned)(((wm + p + (sel & 1) * 8) * 36 + (sel >> 1) * 4) * 4);

    float c[4][4][4];
#pragma unroll
    for (int mi = 0; mi < 4; mi++)
#pragma unroll
        for (int ni = 0; ni < 4; ni++)
#pragma unroll
            for (int r = 0; r < 4; r++) c[mi][ni][r] = 0.f;

#define C_LOAD(st, k0) do { \
    _Pragma("unroll") \
    for (int i = 0; i < 4; i++) { \
        int rowA = lrA + i * 32; \
        CP16(sa + (unsigned)(((st) * 4608 + rowA * 36 + lcA) * 4), \
             Apw + (size_t)(m0 + rowA) * 512 + (k0) + lcA); \
        int rowB = lrB + i * 8; \
        CP16(sb + (unsigned)(((st) * 4352 + rowB * 136 + lcB) * 4), \
             Bg + (size_t)((k0) + rowB) * 9216 + n0 + lcB); \
    } \
    CP_COMMIT(); } while (0)

    C_LOAD(0, 0);
#pragma unroll 1
    for (int kt = 0; kt < 16; kt++) {
        int cur = kt & 1;
        CP_WAIT0();
        __syncthreads();
        if (kt < 15) C_LOAD(cur ^ 1, (kt + 1) * 32);
        const float* BsC = Bs + cur * 4352;
        unsigned abase = sa + (unsigned)(cur * 4608 * 4) + a_off;
#pragma unroll
        for (int ks = 0; ks < 4; ks++) {
            unsigned a[4][4];
#pragma unroll
            for (int mi = 0; mi < 4; mi++) {
                unsigned addr = abase + (unsigned)((mi * 16 * 36 + ks * 8) * 4);
                LDSM_X4(a[mi][0], a[mi][1], a[mi][2], a[mi][3], addr);
            }
            unsigned b[4][2];
#pragma unroll
            for (int ni = 0; ni < 4; ni++) {
                int ncol = wn + ni * 8 + g;
                b[ni][0] = __float_as_uint(BsC[(ks * 8 + t) * 136 + ncol]);
                b[ni][1] = __float_as_uint(BsC[(ks * 8 + t + 4) * 136 + ncol]);
            }
#pragma unroll
            for (int mi = 0; mi < 4; mi++)
#pragma unroll
                for (int ni = 0; ni < 4; ni++)
                    MMA_TF32(c[mi][ni][0], c[mi][ni][1], c[mi][ni][2], c[mi][ni][3],
                             a[mi][0], a[mi][1], a[mi][2], a[mi][3],
                             b[ni][0], b[ni][1]);
        }
    }
#undef C_LOAD

#pragma unroll
    for (int mi = 0; mi < 4; mi++) {
#pragma unroll
        for (int ni = 0; ni < 4; ni++) {
            int m = m0 + wm + mi * 16 + g;
            int n = n0 + wn + ni * 8 + 2 * t;
            size_t off0 = boff + (size_t)m * 9216 + n;
            size_t off1 = boff + (size_t)(m + 8) * 9216 + n;
            float2 cr0 = *(const float2*)(CR + off0);
            float2 cr1 = *(const float2*)(CR + off1);
            float2 o0, o1;
            o0.x = fminf(fmaxf(c[mi][ni][0], 0.f), 6.f) + cr0.x;
            o0.y = fminf(fmaxf(c[mi][ni][1], 0.f), 6.f) + cr0.y;
            o1.x = fminf(fmaxf(c[mi][ni][2], 0.f), 6.f) + cr1.x;
            o1.y = fminf(fmaxf(c[mi][ni][3], 0.f), 6.f) + cr1.y;
            *(float2*)(Out + off0) = o0;
            *(float2*)(Out + off1) = o1;
        }
    }
}

// ---------------------------------------------------------------------------
// Host launch
// ---------------------------------------------------------------------------
extern "C" void kernel_launch(void* const* d_in, const int* in_sizes, int n_in,
                              void* d_out, int out_size) {
    const float* x   = (const float*)d_in[0];
    const float* Wk  = (const float*)d_in[1];
    const float* Wv  = (const float*)d_in[2];
    const float* Wo  = (const float*)d_in[3];
    const float* cWq = (const float*)d_in[4];
    const float* cbq = (const float*)d_in[5];
    const float* cWv = (const float*)d_in[6];
    const float* cWo = (const float*)d_in[7];
    const float* dww = (const float*)d_in[8];
    const float* bng = (const float*)d_in[9];
    const float* bnb = (const float*)d_in[10];
    const float* bnm = (const float*)d_in[11];
    const float* bnv = (const float*)d_in[12];
    const float* pww = (const float*)d_in[13];
    float* out = (float*)d_out;

    float* bufs = nullptr;
    cudaGetSymbolAddress((void**)&bufs, g_bufs);
    float* b0 = bufs + (size_t)0 * TOTE;
    float* b1 = bufs + (size_t)1 * TOTE;
    float* b2 = bufs + (size_t)2 * TOTE;
    float* b3 = bufs + (size_t)3 * TOTE;
    float* b4 = bufs + (size_t)4 * TOTE;
    float* wr = nullptr;
    cudaGetSymbolAddress((void**)&wr, g_w);
    float* rWk  = wr + 0 * 262144;
    float* rWv  = wr + 1 * 262144;
    float* rWo  = wr + 2 * 262144;
    float* rcWq = wr + 3 * 262144;
    float* rcWv = wr + 4 * 262144;
    float* rcWo = wr + 5 * 262144;
    float* rpw  = wr + 6 * 262144;

    const int GEMM_SMEM = 2 * 4608 * 2 * 4;                 // 73728
    const int CONV_SMEM = (2 * 4608 + 2 * 4352) * 4;        // 71680
    const int ATTN_SMEM = (2 * 96 * 68 + 96 * 72) * 4;      // 79872
    cudaFuncSetAttribute(gemm_nt512_tf32, cudaFuncAttributeMaxDynamicSharedMemorySize, GEMM_SMEM);
    cudaFuncSetAttribute(gemm_conv_tf32, cudaFuncAttributeMaxDynamicSharedMemorySize, CONV_SMEM);
    cudaFuncSetAttribute(attn_tc, cudaFuncAttributeMaxDynamicSharedMemorySize, ATTN_SMEM);

    dim3 tb(32, 8);
    dim3 tg(3, 16, 768);
    dim3 gg(4, 576);

    wprep<<<1792, 256>>>(Wk, Wv, Wo, cWq, cWv, cWo, pww);
    img2seq<<<tg, tb>>>(x, b0);
    gemm_nt512_tf32<<<gg, 256, GEMM_SMEM>>>(b0, rWk, b0, nullptr, b1, 1);
    gemm_nt512_tf32<<<gg, 256, GEMM_SMEM>>>(b0, rWv, nullptr, nullptr, b2, 0);
    gemm_nt512_tf32<<<gg, 256, GEMM_SMEM>>>(b0, rcWv, nullptr, nullptr, b3, 0);
    attn_tc<<<dim3(8, 768), 192, ATTN_SMEM>>>(b0, b1, b2, b4);
    gemm_nt512_tf32<<<gg, 256, GEMM_SMEM>>>(b4, rWo, nullptr, nullptr, b0, 0);
    seq2img<true><<<tg, tb>>>(b0, b1);
    gemm_nt512_tf32<<<gg, 256, GEMM_SMEM>>>(b1, rcWq, nullptr, cbq, b2, 2);
    attn_tc<<<dim3(8, 768), 192, ATTN_SMEM>>>(b2, b3, b3, b0);
    gemm_nt512_tf32<<<gg, 256, GEMM_SMEM>>>(b0, rcWo, nullptr, nullptr, b1, 0);
    seq2img<false><<<tg, tb>>>(b1, b2);
    bnprep<<<2, 256>>>(bng, bnb, bnm, bnv);
    dwconv_bn<<<147456, 256>>>(x, dww, b0);
    gemm_conv_tf32<<<dim3(72, 4, 8), 256, CONV_SMEM>>>(rpw, b0, b2, out);
}

// round 5
// speedup vs baseline: 4.6015x; 1.5421x over previous
#include <cuda_runtime.h>
#include <cuda_fp16.h>
#include <math.h>
#include <cstdint>

// ---------------------------------------------------------------------------
// Problem constants: B=8, C=512, H=W=96, heads=8, dh=64
// seq layout: [768, 96, 512]  (n = b*96 + w, t = h, channel c)
// ---------------------------------------------------------------------------
#define TOTE 37748736  // 768*96*512

__device__ __half g_hb[5][TOTE];     // fp16 activation buffers
__device__ float  g_crf[TOTE];       // cross-attn output (fp32 for final add)
__device__ __half g_wh[7 * 262144];  // fp16 weights
__device__ float  g_bnscale[512];
__device__ float  g_bnbias[512];

__device__ __forceinline__ unsigned tf32_rna(float x) {
    unsigned r;
    asm("cvt.rna.tf32.f32 %0, %1;" : "=r"(r) : "f"(x));
    return r;
}
__device__ __forceinline__ float tf32f(float x) { return __uint_as_float(tf32_rna(x)); }

__device__ __forceinline__ float fast_exp(float x) {
    x = fmaxf(x, -87.0f);
    float t = x * 1.44269504088896f;
    float fi = floorf(t);
    float f = t - fi;
    float p = 1.54035304e-4f;
    p = fmaf(p, f, 1.33335581e-3f);
    p = fmaf(p, f, 9.61812910e-3f);
    p = fmaf(p, f, 5.55041087e-2f);
    p = fmaf(p, f, 2.40226507e-1f);
    p = fmaf(p, f, 6.93147181e-1f);
    p = fmaf(p, f, 1.0f);
    return p * __int_as_float(((int)fi + 127) << 23);
}

#define MMA_TF32(c0,c1,c2,c3,a0,a1,a2,a3,b0,b1) \
    asm volatile("mma.sync.aligned.m16n8k8.row.col.f32.tf32.tf32.f32 " \
                 "{%0,%1,%2,%3},{%4,%5,%6,%7},{%8,%9},{%0,%1,%2,%3};" \
                 : "+f"(c0),"+f"(c1),"+f"(c2),"+f"(c3) \
                 : "r"(a0),"r"(a1),"r"(a2),"r"(a3),"r"(b0),"r"(b1))

#define MMA_F16(c0,c1,c2,c3,a0,a1,a2,a3,b0,b1) \
    asm volatile("mma.sync.aligned.m16n8k16.row.col.f32.f16.f16.f32 " \
                 "{%0,%1,%2,%3},{%4,%5,%6,%7},{%8,%9},{%0,%1,%2,%3};" \
                 : "+f"(c0),"+f"(c1),"+f"(c2),"+f"(c3) \
                 : "r"(a0),"r"(a1),"r"(a2),"r"(a3),"r"(b0),"r"(b1))

#define LDSM_X4(r0,r1,r2,r3,addr) \
    asm volatile("ldmatrix.sync.aligned.m8n8.x4.shared.b16 {%0,%1,%2,%3}, [%4];" \
                 : "=r"(r0),"=r"(r1),"=r"(r2),"=r"(r3) : "r"(addr))

#define LDSM_X4T(r0,r1,r2,r3,addr) \
    asm volatile("ldmatrix.sync.aligned.m8n8.x4.trans.shared.b16 {%0,%1,%2,%3}, [%4];" \
                 : "=r"(r0),"=r"(r1),"=r"(r2),"=r"(r3) : "r"(addr))

#define CP16(dst, src) \
    asm volatile("cp.async.cg.shared.global [%0], [%1], 16;" :: "r"(dst), "l"(src))
#define CP_COMMIT() asm volatile("cp.async.commit_group;")
#define CP_WAIT0()  asm volatile("cp.async.wait_group 0;")

// ---------------------------------------------------------------------------
// Weight prep: fp16-round 7 [512x512] matrices into g_wh
// ---------------------------------------------------------------------------
__global__ void wprep(const float* __restrict__ a0, const float* __restrict__ a1,
                      const float* __restrict__ a2, const float* __restrict__ a3,
                      const float* __restrict__ a4, const float* __restrict__ a5,
                      const float* __restrict__ a6) {
    int i = blockIdx.x * 256 + threadIdx.x;  // 458752 float4s
    int mat = i >> 16;
    int off = (i & 65535) * 4;
    const float* s;
    switch (mat) {
        case 0: s = a0; break; case 1: s = a1; break; case 2: s = a2; break;
        case 3: s = a3; break; case 4: s = a4; break; case 5: s = a5; break;
        default: s = a6; break;
    }
    float4 v = *(const float4*)(s + off);
    __half2 h0 = __floats2half2_rn(v.x, v.y);
    __half2 h1 = __floats2half2_rn(v.z, v.w);
    *(__half2*)(g_wh + (size_t)mat * 262144 + off)     = h0;
    *(__half2*)(g_wh + (size_t)mat * 262144 + off + 2) = h1;
}

// ---------------------------------------------------------------------------
// Layout transposes (c <-> w per (b,h) plane)
// ---------------------------------------------------------------------------
// img fp32 -> seq fp16
__global__ void img2seq(const float* __restrict__ img, __half* __restrict__ seq) {
    __shared__ float tile[32][33];
    int bh = blockIdx.z;
    int b = bh / 96, h = bh % 96;
    int c0 = blockIdx.y * 32, w0 = blockIdx.x * 32;
    int tx = threadIdx.x, ty = threadIdx.y;
#pragma unroll
    for (int i = 0; i < 4; i++) {
        int c = c0 + ty + i * 8;
        tile[ty + i * 8][tx] = img[(((size_t)b * 512 + c) * 96 + h) * 96 + w0 + tx];
    }
    __syncthreads();
#pragma unroll
    for (int i = 0; i < 4; i++) {
        int w = w0 + ty + i * 8;
        seq[(((size_t)(b * 96 + w)) * 96 + h) * 512 + c0 + tx] =
            __float2half_rn(tile[tx][ty + i * 8]);
    }
}

// seq fp16 -> img fp16
__global__ void seq2img_hh(const __half* __restrict__ seq, __half* __restrict__ img) {
    __shared__ float tile[32][33];
    int bh = blockIdx.z;
    int b = bh / 96, h = bh % 96;
    int c0 = blockIdx.y * 32, w0 = blockIdx.x * 32;
    int tx = threadIdx.x, ty = threadIdx.y;
#pragma unroll
    for (int i = 0; i < 4; i++) {
        int w = w0 + ty + i * 8;
        tile[ty + i * 8][tx] =
            __half2float(seq[(((size_t)(b * 96 + w)) * 96 + h) * 512 + c0 + tx]);
    }
    __syncthreads();
#pragma unroll
    for (int i = 0; i < 4; i++) {
        int c = c0 + ty + i * 8;
        img[(((size_t)b * 512 + c) * 96 + h) * 96 + w0 + tx] =
            __float2half_rn(tile[tx][ty + i * 8]);
    }
}

// seq fp16 -> img fp32 (for cr)
__global__ void seq2img_hf(const __half* __restrict__ seq, float* __restrict__ img) {
    __shared__ float tile[32][33];
    int bh = blockIdx.z;
    int b = bh / 96, h = bh % 96;
    int c0 = blockIdx.y * 32, w0 = blockIdx.x * 32;
    int tx = threadIdx.x, ty = threadIdx.y;
#pragma unroll
    for (int i = 0; i < 4; i++) {
        int w = w0 + ty + i * 8;
        tile[ty + i * 8][tx] =
            __half2float(seq[(((size_t)(b * 96 + w)) * 96 + h) * 512 + c0 + tx]);
    }
    __syncthreads();
#pragma unroll
    for (int i = 0; i < 4; i++) {
        int c = c0 + ty + i * 8;
        img[(((size_t)b * 512 + c) * 96 + h) * 96 + w0 + tx] = tile[tx][ty + i * 8];
    }
}

// ---------------------------------------------------------------------------
// fp16 GEMM: C[M,512] = A @ W^T (+A | +bias). Block 128x128, k-chunk 64,
// 2-stage cp.async, 8 warps (2m x 4n), m16n8k16, fp32 accum.
// smem: As[2][128*72]h, Ws[2][128*72]h  (pitch 72 halves = 144B, conflict-free)
// ---------------------------------------------------------------------------
__global__ __launch_bounds__(256, 2) void gemm_h(
    const __half* __restrict__ A, const __half* __restrict__ W,
    const __half* __restrict__ Add, const float* __restrict__ bias,
    __half* __restrict__ Cout, int mode)
{
    extern __shared__ char smc[];
    __half* As = (__half*)smc;                 // 2 x 9216 halves
    __half* Ws = (__half*)(smc + 36864);
    int m0 = blockIdx.y * 128;
    int n0 = blockIdx.x * 128;
    int tid = threadIdx.x;
    int w = tid >> 5, l = tid & 31;
    int g = l >> 2, t = l & 3;
    int wm = (w & 1) * 64, wn = (w >> 1) * 32;
    int u = tid & 7, r0 = tid >> 3;            // chunk, row(0..31)

    unsigned sa  = (unsigned)__cvta_generic_to_shared(As);
    unsigned swb = (unsigned)__cvta_generic_to_shared(Ws);
    int p = l & 7, sel = l >> 3;
    unsigned a_off = (unsigned)(((wm + p + (sel & 1) * 8) * 72 + (sel >> 1) * 8) * 2);

    float c[4][4][4];
#pragma unroll
    for (int mi = 0; mi < 4; mi++)
#pragma unroll
        for (int ni = 0; ni < 4; ni++)
#pragma unroll
            for (int r = 0; r < 4; r++) c[mi][ni][r] = 0.f;

#define GH_LOAD(st, kc) do { \
    const __half* Ag = A + (size_t)(m0 + r0) * 512 + (kc) * 64 + u * 8; \
    const __half* Wg = W + (size_t)(n0 + r0) * 512 + (kc) * 64 + u * 8; \
    unsigned da = sa  + (unsigned)(((st) * 9216 + r0 * 72 + u * 8) * 2); \
    unsigned dw = swb + (unsigned)(((st) * 9216 + r0 * 72 + u * 8) * 2); \
    _Pragma("unroll") \
    for (int i = 0; i < 4; i++) { \
        CP16(da + (unsigned)(i * 32 * 144), Ag + (size_t)i * 32 * 512); \
        CP16(dw + (unsigned)(i * 32 * 144), Wg + (size_t)i * 32 * 512); \
    } \
    CP_COMMIT(); } while (0)

    GH_LOAD(0, 0);
#pragma unroll 1
    for (int kt = 0; kt < 8; kt++) {
        int cur = kt & 1;
        CP_WAIT0();
        __syncthreads();
        if (kt < 7) GH_LOAD(cur ^ 1, kt + 1);
        const __half* WsC = Ws + cur * 9216;
        unsigned abase = sa + (unsigned)(cur * 9216 * 2) + a_off;
#pragma unroll
        for (int ks = 0; ks < 4; ks++) {
            int k0 = ks * 16;
            unsigned a[4][4];
#pragma unroll
            for (int mi = 0; mi < 4; mi++) {
                unsigned addr = abase + (unsigned)((mi * 16 * 72 + k0) * 2);
                LDSM_X4(a[mi][0], a[mi][1], a[mi][2], a[mi][3], addr);
            }
            unsigned b[4][2];
#pragma unroll
            for (int ni = 0; ni < 4; ni++) {
                const __half* wp = WsC + (wn + ni * 8 + g) * 72 + k0 + 2 * t;
                b[ni][0] = *(const unsigned*)wp;
                b[ni][1] = *(const unsigned*)(wp + 8);
            }
#pragma unroll
            for (int mi = 0; mi < 4; mi++)
#pragma unroll
                for (int ni = 0; ni < 4; ni++)
                    MMA_F16(c[mi][ni][0], c[mi][ni][1], c[mi][ni][2], c[mi][ni][3],
                            a[mi][0], a[mi][1], a[mi][2], a[mi][3],
                            b[ni][0], b[ni][1]);
        }
        __syncthreads();
    }
#undef GH_LOAD

#pragma unroll
    for (int mi = 0; mi < 4; mi++) {
#pragma unroll
        for (int ni = 0; ni < 4; ni++) {
            int m = m0 + wm + mi * 16 + g;
            int n = n0 + wn + ni * 8 + 2 * t;
            float v00 = c[mi][ni][0], v01 = c[mi][ni][1];
            float v10 = c[mi][ni][2], v11 = c[mi][ni][3];
            if (mode == 1) {
                float2 a0 = __half22float2(*(const __half2*)(Add + (size_t)m * 512 + n));
                float2 a1 = __half22float2(*(const __half2*)(Add + (size_t)(m + 8) * 512 + n));
                v00 += a0.x; v01 += a0.y; v10 += a1.x; v11 += a1.y;
            } else if (mode == 2) {
                float2 bb = *(const float2*)(bias + n);
                v00 += bb.x; v01 += bb.y; v10 += bb.x; v11 += bb.y;
            }
            *(__half2*)(Cout + (size_t)m * 512 + n) = __floats2half2_rn(v00, v01);
            *(__half2*)(Cout + (size_t)(m + 8) * 512 + n) = __floats2half2_rn(v10, v11);
        }
    }
}

// ---------------------------------------------------------------------------
// Tensor-core attention (tf32 compute, fp16 I/O): block per (n,head),
// 192 threads (6 warps), warp w handles q-rows [16w,16w+16).
// ---------------------------------------------------------------------------
__global__ __launch_bounds__(192, 2) void attn_tc(
    const __half* __restrict__ Qg, const __half* __restrict__ Kg,
    const __half* __restrict__ Vg, __half* __restrict__ Og)
{
    extern __shared__ float sm[];
    float* Qs = sm;               // [96][68]
    float* Ks = sm + 96 * 68;     // [96][68]
    float* Vs = sm + 2 * 96 * 68; // [96][72]
    float* Ps = sm;               // alias over Qs/Ks: [96][100]

    int hd = blockIdx.x, n = blockIdx.y;
    size_t base = (size_t)n * 96 * 512 + hd * 64;
    int tid = threadIdx.x;
    int w = tid >> 5, l = tid & 31;
    int g = l >> 2, t = l & 3;
    int qr = w * 16;

    for (int i = tid; i < 96 * 8; i += 192) {
        int r = i >> 3, cc = (i & 7) * 8;
        uint4 q = *(const uint4*)(Qg + base + (size_t)r * 512 + cc);
        uint4 k = *(const uint4*)(Kg + base + (size_t)r * 512 + cc);
        uint4 v = *(const uint4*)(Vg + base + (size_t)r * 512 + cc);
        const __half2* qh = (const __half2*)&q;
        const __half2* kh = (const __half2*)&k;
        const __half2* vh = (const __half2*)&v;
#pragma unroll
        for (int j = 0; j < 4; j++) {
            float2 fq = __half22float2(qh[j]);
            float2 fk = __half22float2(kh[j]);
            float2 fv = __half22float2(vh[j]);
            Qs[r * 68 + cc + 2 * j] = fq.x; Qs[r * 68 + cc + 2 * j + 1] = fq.y;
            Ks[r * 68 + cc + 2 * j] = fk.x; Ks[r * 68 + cc + 2 * j + 1] = fk.y;
            Vs[r * 72 + cc + 2 * j] = fv.x; Vs[r * 72 + cc + 2 * j + 1] = fv.y;
        }
    }
    __syncthreads();

    float c[12][4];
#pragma unroll
    for (int ni = 0; ni < 12; ni++)
#pragma unroll
        for (int r = 0; r < 4; r++) c[ni][r] = 0.f;

#pragma unroll
    for (int k0 = 0; k0 < 64; k0 += 8) {
        unsigned a0 = __float_as_uint(Qs[(qr + g) * 68 + k0 + t]);
        unsigned a1 = __float_as_uint(Qs[(qr + g + 8) * 68 + k0 + t]);
        unsigned a2 = __float_as_uint(Qs[(qr + g) * 68 + k0 + t + 4]);
        unsigned a3 = __float_as_uint(Qs[(qr + g + 8) * 68 + k0 + t + 4]);
#pragma unroll
        for (int ni = 0; ni < 12; ni++) {
            unsigned b0 = __float_as_uint(Ks[(ni * 8 + g) * 68 + k0 + t]);
            unsigned b1 = __float_as_uint(Ks[(ni * 8 + g) * 68 + k0 + t + 4]);
            MMA_TF32(c[ni][0], c[ni][1], c[ni][2], c[ni][3], a0, a1, a2, a3, b0, b1);
        }
    }

    float m0 = -1e30f, m1 = -1e30f;
#pragma unroll
    for (int ni = 0; ni < 12; ni++) {
#pragma unroll
        for (int r = 0; r < 4; r++) c[ni][r] *= 0.125f;
        m0 = fmaxf(m0, fmaxf(c[ni][0], c[ni][1]));
        m1 = fmaxf(m1, fmaxf(c[ni][2], c[ni][3]));
    }
    m0 = fmaxf(m0, __shfl_xor_sync(0xffffffff, m0, 1));
    m0 = fmaxf(m0, __shfl_xor_sync(0xffffffff, m0, 2));
    m1 = fmaxf(m1, __shfl_xor_sync(0xffffffff, m1, 1));
    m1 = fmaxf(m1, __shfl_xor_sync(0xffffffff, m1, 2));
    float s0 = 0.f, s1 = 0.f;
#pragma unroll
    for (int ni = 0; ni < 12; ni++) {
        c[ni][0] = fast_exp(c[ni][0] - m0);
        c[ni][1] = fast_exp(c[ni][1] - m0);
        c[ni][2] = fast_exp(c[ni][2] - m1);
        c[ni][3] = fast_exp(c[ni][3] - m1);
        s0 += c[ni][0] + c[ni][1];
        s1 += c[ni][2] + c[ni][3];
    }
    s0 += __shfl_xor_sync(0xffffffff, s0, 1);
    s0 += __shfl_xor_sync(0xffffffff, s0, 2);
    s1 += __shfl_xor_sync(0xffffffff, s1, 1);
    s1 += __shfl_xor_sync(0xffffffff, s1, 2);

    __syncthreads();

#pragma unroll
    for (int ni = 0; ni < 12; ni++) {
        float2 p0 = {tf32f(c[ni][0]), tf32f(c[ni][1])};
        float2 p1 = {tf32f(c[ni][2]), tf32f(c[ni][3])};
        *(float2*)&Ps[(qr + g) * 100 + ni * 8 + 2 * t] = p0;
        *(float2*)&Ps[(qr + g + 8) * 100 + ni * 8 + 2 * t] = p1;
    }
    __syncwarp();

    float o[8][4];
#pragma unroll
    for (int ni = 0; ni < 8; ni++)
#pragma unroll
        for (int r = 0; r < 4; r++) o[ni][r] = 0.f;
#pragma unroll
    for (int k0 = 0; k0 < 96; k0 += 8) {
        unsigned a0 = __float_as_uint(Ps[(qr + g) * 100 + k0 + t]);
        unsigned a1 = __float_as_uint(Ps[(qr + g + 8) * 100 + k0 + t]);
        unsigned a2 = __float_as_uint(Ps[(qr + g) * 100 + k0 + t + 4]);
        unsigned a3 = __float_as_uint(Ps[(qr + g + 8) * 100 + k0 + t + 4]);
#pragma unroll
        for (int ni = 0; ni < 8; ni++) {
            unsigned b0 = __float_as_uint(Vs[(k0 + t) * 72 + ni * 8 + g]);
            unsigned b1 = __float_as_uint(Vs[(k0 + t + 4) * 72 + ni * 8 + g]);
            MMA_TF32(o[ni][0], o[ni][1], o[ni][2], o[ni][3], a0, a1, a2, a3, b0, b1);
        }
    }

    float inv0 = 1.0f / s0, inv1 = 1.0f / s1;
    __half* ob = Og + base;
#pragma unroll
    for (int ni = 0; ni < 8; ni++) {
        *(__half2*)(ob + (size_t)(qr + g) * 512 + ni * 8 + 2 * t) =
            __floats2half2_rn(o[ni][0] * inv0, o[ni][1] * inv0);
        *(__half2*)(ob + (size_t)(qr + g + 8) * 512 + ni * 8 + 2 * t) =
            __floats2half2_rn(o[ni][2] * inv1, o[ni][3] * inv1);
    }
}

// ---------------------------------------------------------------------------
__global__ void bnprep(const float* __restrict__ g, const float* __restrict__ b,
                       const float* __restrict__ m, const float* __restrict__ v) {
    int c = blockIdx.x * 256 + threadIdx.x;
    if (c < 512) {
        float sc = g[c] * rsqrtf(v[c] + 1e-5f);
        g_bnscale[c] = sc;
        g_bnbias[c]  = b[c] - m[c] * sc;
    }
}

__global__ void dwconv_bn(const float* __restrict__ x, const float* __restrict__ wd,
                          __half* __restrict__ o) {
    int idx = blockIdx.x * 256 + threadIdx.x;
    int w = idx % 96;
    int t = idx / 96;
    int h = t % 96;
    int bc = t / 96;
    int c = bc & 511;
    const float* wt = wd + c * 9;
    const float* xp = x + (size_t)bc * 9216;
    float s = 0.f;
#pragma unroll
    for (int kh = -1; kh <= 1; kh++) {
        int hh = h + kh;
        if (hh < 0 || hh >= 96) continue;
#pragma unroll
        for (int kw = -1; kw <= 1; kw++) {
            int ww = w + kw;
            if (ww < 0 || ww >= 96) continue;
            s = fmaf(xp[hh * 96 + ww], wt[(kh + 1) * 3 + (kw + 1)], s);
        }
    }
    o[idx] = __float2half_rn(fmaf(s, g_bnscale[c], g_bnbias[c]));
}

// ---------------------------------------------------------------------------
// fp16 1x1-conv GEMM per batch: Out = clip(pw @ y, 0, 6) + CR
// A = pw [m=512,k=512] half; B = y slice [k=512, n=9216] half (n-contig);
// Block 128x128, k-chunk 64, B frags via ldmatrix.x4.trans.
// smem: As[2][128*72]h, Bs[2][64*136]h
// ---------------------------------------------------------------------------
__global__ __launch_bounds__(256, 2) void gemm_conv_h(
    const __half* __restrict__ Apw, const __half* __restrict__ Bt,
    const float* __restrict__ CR, float* __restrict__ Out)
{
    extern __shared__ char smc[];
    __half* As = (__half*)smc;                 // 2 x 9216 halves
    __half* Bs = (__half*)(smc + 36864);       // 2 x 8704 halves
    int bat = blockIdx.z;
    size_t boff = (size_t)bat * 512 * 9216;
    const __half* Bg = Bt + boff;
    int n0 = blockIdx.x * 128;
    int m0 = blockIdx.y * 128;
    int tid = threadIdx.x;
    int w = tid >> 5, l = tid & 31;
    int g = l >> 2, t = l & 3;
    int wm = (w & 1) * 64, wn = (w >> 1) * 32;

    int uA = tid & 7, rA = tid >> 3;           // A: chunk, row 0..31
    int uB = tid & 15, rB = tid >> 4;          // B: chunk, krow 0..15

    unsigned sa = (unsigned)__cvta_generic_to_shared(As);
    unsigned sb = (unsigned)__cvta_generic_to_shared(Bs);
    int p = l & 7, sel = l >> 3;
    unsigned a_off = (unsigned)(((wm + p + (sel & 1) * 8) * 72 + (sel >> 1) * 8) * 2);
    // B ldmatrix.trans address components: row k = p + (sel&1)*8, col = (sel>>1)*8
    unsigned b_off = (unsigned)(((p + (sel & 1) * 8) * 136 + (sel >> 1) * 8) * 2);

    float c[4][4][4];
#pragma unroll
    for (int mi = 0; mi < 4; mi++)
#pragma unroll
        for (int ni = 0; ni < 4; ni++)
#pragma unroll
            for (int r = 0; r < 4; r++) c[mi][ni][r] = 0.f;

#define GC_LOAD(st, kc) do { \
    const __half* Ag = Apw + (size_t)(m0 + rA) * 512 + (kc) * 64 + uA * 8; \
    unsigned da = sa + (unsigned)(((st) * 9216 + rA * 72 + uA * 8) * 2); \
    _Pragma("unroll") \
    for (int i = 0; i < 4; i++) \
        CP16(da + (unsigned)(i * 32 * 144), Ag + (size_t)i * 32 * 512); \
    const __half* Bgp = Bg + (size_t)((kc) * 64 + rB) * 9216 + n0 + uB * 8; \
    unsigned db = sb + (unsigned)(((st) * 8704 + rB * 136 + uB * 8) * 2); \
    _Pragma("unroll") \
    for (int i = 0; i < 4; i++) \
        CP16(db + (unsigned)(i * 16 * 272), Bgp + (size_t)i * 16 * 9216); \
    CP_COMMIT(); } while (0)

    GC_LOAD(0, 0);
#pragma unroll 1
    for (int kt = 0; kt < 8; kt++) {
        int cur = kt & 1;
        CP_WAIT0();
        __syncthreads();
        if (kt < 7) GC_LOAD(cur ^ 1, kt + 1);
        unsigned abase = sa + (unsigned)(cur * 9216 * 2) + a_off;
        unsigned bbase = sb + (unsigned)(cur * 8704 * 2) + b_off;
#pragma unroll
        for (int ks = 0; ks < 4; ks++) {
            int k0 = ks * 16;
            unsigned a[4][4];
#pragma unroll
            for (int mi = 0; mi < 4; mi++) {
                unsigned addr = abase + (unsigned)((mi * 16 * 72 + k0) * 2);
                LDSM_X4(a[mi][0], a[mi][1], a[mi][2], a[mi][3], addr);
            }
            unsigned b[4][2];
#pragma unroll
            for (int nj = 0; nj < 2; nj++) {
                unsigned addr = bbase + (unsigned)((k0 * 136 + wn + nj * 16) * 2);
                unsigned q0, q1, q2, q3;
                LDSM_X4T(q0, q1, q2, q3, addr);
                b[nj * 2][0] = q0;     b[nj * 2][1] = q1;
                b[nj * 2 + 1][0] = q2; b[nj * 2 + 1][1] = q3;
            }
#pragma unroll
            for (int mi = 0; mi < 4; mi++)
#pragma unroll
                for (int ni = 0; ni < 4; ni++)
                    MMA_F16(c[mi][ni][0], c[mi][ni][1], c[mi][ni][2], c[mi][ni][3],
                            a[mi][0], a[mi][1], a[mi][2], a[mi][3],
                            b[ni][0], b[ni][1]);
        }
        __syncthreads();
    }
#undef GC_LOAD

#pragma unroll
    for (int mi = 0; mi < 4; mi++) {
#pragma unroll
        for (int ni = 0; ni < 4; ni++) {
            int m = m0 + wm + mi * 16 + g;
            int n = n0 + wn + ni * 8 + 2 * t;
            size_t off0 = boff + (size_t)m * 9216 + n;
            size_t off1 = boff + (size_t)(m + 8) * 9216 + n;
            float2 cr0 = *(const float2*)(CR + off0);
            float2 cr1 = *(const float2*)(CR + off1);
            float2 o0, o1;
            o0.x = fminf(fmaxf(c[mi][ni][0], 0.f), 6.f) + cr0.x;
            o0.y = fminf(fmaxf(c[mi][ni][1], 0.f), 6.f) + cr0.y;
            o1.x = fminf(fmaxf(c[mi][ni][2], 0.f), 6.f) + cr1.x;
            o1.y = fminf(fmaxf(c[mi][ni][3], 0.f), 6.f) + cr1.y;
            *(float2*)(Out + off0) = o0;
            *(float2*)(Out + off1) = o1;
        }
    }
}

// ---------------------------------------------------------------------------
// Host launch
// ---------------------------------------------------------------------------
extern "C" void kernel_launch(void* const* d_in, const int* in_sizes, int n_in,
                              void* d_out, int out_size) {
    const float* x   = (const float*)d_in[0];
    const float* Wk  = (const float*)d_in[1];
    const float* Wv  = (const float*)d_in[2];
    const float* Wo  = (const float*)d_in[3];
    const float* cWq = (const float*)d_in[4];
    const float* cbq = (const float*)d_in[5];
    const float* cWv = (const float*)d_in[6];
    const float* cWo = (const float*)d_in[7];
    const float* dww = (const float*)d_in[8];
    const float* bng = (const float*)d_in[9];
    const float* bnb = (const float*)d_in[10];
    const float* bnm = (const float*)d_in[11];
    const float* bnv = (const float*)d_in[12];
    const float* pww = (const float*)d_in[13];
    float* out = (float*)d_out;

    __half* hb = nullptr;
    cudaGetSymbolAddress((void**)&hb, g_hb);
    __half* h0 = hb + (size_t)0 * TOTE;
    __half* h1 = hb + (size_t)1 * TOTE;
    __half* h2 = hb + (size_t)2 * TOTE;
    __half* h3 = hb + (size_t)3 * TOTE;
    __half* h4 = hb + (size_t)4 * TOTE;
    float* crf = nullptr;
    cudaGetSymbolAddress((void**)&crf, g_crf);
    __half* wh = nullptr;
    cudaGetSymbolAddress((void**)&wh, g_wh);
    __half* rWk  = wh + (size_t)0 * 262144;
    __half* rWv  = wh + (size_t)1 * 262144;
    __half* rWo  = wh + (size_t)2 * 262144;
    __half* rcWq = wh + (size_t)3 * 262144;
    __half* rcWv = wh + (size_t)4 * 262144;
    __half* rcWo = wh + (size_t)5 * 262144;
    __half* rpw  = wh + (size_t)6 * 262144;

    const int GEMM_SMEM = 4 * 9216 * 2;                     // 73728
    const int CONV_SMEM = (2 * 9216 + 2 * 8704) * 2;        // 71680
    const int ATTN_SMEM = (2 * 96 * 68 + 96 * 72) * 4;      // 79872
    cudaFuncSetAttribute(gemm_h, cudaFuncAttributeMaxDynamicSharedMemorySize, GEMM_SMEM);
    cudaFuncSetAttribute(gemm_conv_h, cudaFuncAttributeMaxDynamicSharedMemorySize, CONV_SMEM);
    cudaFuncSetAttribute(attn_tc, cudaFuncAttributeMaxDynamicSharedMemorySize, ATTN_SMEM);

    dim3 tb(32, 8);
    dim3 tg(3, 16, 768);
    dim3 gg(4, 576);

    wprep<<<1792, 256>>>(Wk, Wv, Wo, cWq, cWv, cWo, pww);
    img2seq<<<tg, tb>>>(x, h0);
    gemm_h<<<gg, 256, GEMM_SMEM>>>(h0, rWk, h0, nullptr, h1, 1);
    gemm_h<<<gg, 256, GEMM_SMEM>>>(h0, rWv, nullptr, nullptr, h2, 0);
    gemm_h<<<gg, 256, GEMM_SMEM>>>(h0, rcWv, nullptr, nullptr, h3, 0);
    attn_tc<<<dim3(8, 768), 192, ATTN_SMEM>>>(h0, h1, h2, h4);
    gemm_h<<<gg, 256, GEMM_SMEM>>>(h4, rWo, nullptr, nullptr, h1, 0);
    seq2img_hh<<<tg, tb>>>(h1, h2);
    gemm_h<<<gg, 256, GEMM_SMEM>>>(h2, rcWq, nullptr, cbq, h4, 2);
    attn_tc<<<dim3(8, 768), 192, ATTN_SMEM>>>(h4, h3, h3, h1);
    gemm_h<<<gg, 256, GEMM_SMEM>>>(h1, rcWo, nullptr, nullptr, h2, 0);
    seq2img_hf<<<tg, tb>>>(h2, crf);
    bnprep<<<2, 256>>>(bng, bnb, bnm, bnv);
    dwconv_bn<<<147456, 256>>>(x, dww, h0);
    gemm_conv_h<<<dim3(72, 4, 8), 256, CONV_SMEM>>>(rpw, h0, crf, out);
}

// round 7
// speedup vs baseline: 4.6251x; 1.0051x over previous
#include <cuda_runtime.h>
#include <cuda_fp16.h>
#include <math.h>
#include <cstdint>

// ---------------------------------------------------------------------------
// Problem constants: B=8, C=512, H=W=96, heads=8, dh=64
// seq layout: [768, 96, 512]  (n = b*96 + w, t = h, channel c)
// ---------------------------------------------------------------------------
#define TOTE 37748736  // 768*96*512

__device__ __half g_hb[5][TOTE];     // fp16 activation buffers
__device__ float  g_crf[TOTE];       // cross-attn output (fp32 for final add)
__device__ __half g_wh[7 * 262144];  // fp16 weights, slot order: Wk,Wv,cWv,Wo,cWq,cWo,pw
__device__ float  g_bnscale[512];
__device__ float  g_bnbias[512];

__device__ __forceinline__ float fast_exp(float x) {
    x = fmaxf(x, -87.0f);
    float t = x * 1.44269504088896f;
    float fi = floorf(t);
    float f = t - fi;
    float p = 1.54035304e-4f;
    p = fmaf(p, f, 1.33335581e-3f);
    p = fmaf(p, f, 9.61812910e-3f);
    p = fmaf(p, f, 5.55041087e-2f);
    p = fmaf(p, f, 2.40226507e-1f);
    p = fmaf(p, f, 6.93147181e-1f);
    p = fmaf(p, f, 1.0f);
    return p * __int_as_float(((int)fi + 127) << 23);
}

#define MMA_F16(c0,c1,c2,c3,a0,a1,a2,a3,b0,b1) \
    asm volatile("mma.sync.aligned.m16n8k16.row.col.f32.f16.f16.f32 " \
                 "{%0,%1,%2,%3},{%4,%5,%6,%7},{%8,%9},{%0,%1,%2,%3};" \
                 : "+f"(c0),"+f"(c1),"+f"(c2),"+f"(c3) \
                 : "r"(a0),"r"(a1),"r"(a2),"r"(a3),"r"(b0),"r"(b1))

#define LDSM_X4(r0,r1,r2,r3,addr) \
    asm volatile("ldmatrix.sync.aligned.m8n8.x4.shared.b16 {%0,%1,%2,%3}, [%4];" \
                 : "=r"(r0),"=r"(r1),"=r"(r2),"=r"(r3) : "r"(addr))

#define LDSM_X4T(r0,r1,r2,r3,addr) \
    asm volatile("ldmatrix.sync.aligned.m8n8.x4.trans.shared.b16 {%0,%1,%2,%3}, [%4];" \
                 : "=r"(r0),"=r"(r1),"=r"(r2),"=r"(r3) : "r"(addr))

#define CP16(dst, src) \
    asm volatile("cp.async.cg.shared.global [%0], [%1], 16;" :: "r"(dst), "l"(src))
#define CP_COMMIT() asm volatile("cp.async.commit_group;")
#define CP_WAIT0()  asm volatile("cp.async.wait_group 0;")
#define CP_WAIT2()  asm volatile("cp.async.wait_group 2;")

__device__ __forceinline__ unsigned h2pack(float a, float b) {
    unsigned r;
    asm("cvt.rn.f16x2.f32 %0, %2, %1;" : "=r"(r) : "f"(a), "f"(b));
    return r;
}

// ---------------------------------------------------------------------------
// Weight prep: fp16-round 7 [512x512] matrices into g_wh (slot order = arg order)
// ---------------------------------------------------------------------------
__global__ void wprep(const float* __restrict__ a0, const float* __restrict__ a1,
                      const float* __restrict__ a2, const float* __restrict__ a3,
                      const float* __restrict__ a4, const float* __restrict__ a5,
                      const float* __restrict__ a6) {
    int i = blockIdx.x * 256 + threadIdx.x;
    int mat = i >> 16;
    int off = (i & 65535) * 4;
    const float* s;
    switch (mat) {
        case 0: s = a0; break; case 1: s = a1; break; case 2: s = a2; break;
        case 3: s = a3; break; case 4: s = a4; break; case 5: s = a5; break;
        default: s = a6; break;
    }
    float4 v = *(const float4*)(s + off);
    *(__half2*)(g_wh + (size_t)mat * 262144 + off)     = __floats2half2_rn(v.x, v.y);
    *(__half2*)(g_wh + (size_t)mat * 262144 + off + 2) = __floats2half2_rn(v.z, v.w);
}

// ---------------------------------------------------------------------------
// Layout transposes (c <-> w per (b,h) plane)
// ---------------------------------------------------------------------------
__global__ void img2seq(const float* __restrict__ img, __half* __restrict__ seq) {
    __shared__ float tile[32][33];
    int bh = blockIdx.z;
    int b = bh / 96, h = bh % 96;
    int c0 = blockIdx.y * 32, w0 = blockIdx.x * 32;
    int tx = threadIdx.x, ty = threadIdx.y;
#pragma unroll
    for (int i = 0; i < 4; i++) {
        int c = c0 + ty + i * 8;
        tile[ty + i * 8][tx] = img[(((size_t)b * 512 + c) * 96 + h) * 96 + w0 + tx];
    }
    __syncthreads();
#pragma unroll
    for (int i = 0; i < 4; i++) {
        int w = w0 + ty + i * 8;
        seq[(((size_t)(b * 96 + w)) * 96 + h) * 512 + c0 + tx] =
            __float2half_rn(tile[tx][ty + i * 8]);
    }
}

__global__ void seq2img_hh(const __half* __restrict__ seq, __half* __restrict__ img) {
    __shared__ __half tile[32][33];
    int bh = blockIdx.z;
    int b = bh / 96, h = bh % 96;
    int c0 = blockIdx.y * 32, w0 = blockIdx.x * 32;
    int tx = threadIdx.x, ty = threadIdx.y;
#pragma unroll
    for (int i = 0; i < 4; i++) {
        int w = w0 + ty + i * 8;
        tile[ty + i * 8][tx] = seq[(((size_t)(b * 96 + w)) * 96 + h) * 512 + c0 + tx];
    }
    __syncthreads();
#pragma unroll
    for (int i = 0; i < 4; i++) {
        int c = c0 + ty + i * 8;
        img[(((size_t)b * 512 + c) * 96 + h) * 96 + w0 + tx] = tile[tx][ty + i * 8];
    }
}

__global__ void seq2img_hf(const __half* __restrict__ seq, float* __restrict__ img) {
    __shared__ float tile[32][33];
    int bh = blockIdx.z;
    int b = bh / 96, h = bh % 96;
    int c0 = blockIdx.y * 32, w0 = blockIdx.x * 32;
    int tx = threadIdx.x, ty = threadIdx.y;
#pragma unroll
    for (int i = 0; i < 4; i++) {
        int w = w0 + ty + i * 8;
        tile[ty + i * 8][tx] =
            __half2float(seq[(((size_t)(b * 96 + w)) * 96 + h) * 512 + c0 + tx]);
    }
    __syncthreads();
#pragma unroll
    for (int i = 0; i < 4; i++) {
        int c = c0 + ty + i * 8;
        img[(((size_t)b * 512 + c) * 96 + h) * 96 + w0 + tx] = tile[tx][ty + i * 8];
    }
}

// ---------------------------------------------------------------------------
// fp16 GEMM, multi-output: computes A[M,512] @ Wb[1536 or 512,512]^T.
// blockIdx.x selects a 128-col n-tile; nmat = blockIdx.x>>2 selects output
// buffer + epilogue mode (mode 0 plain, 1 +Add, 2 +bias).
// Block tile 128x128, k-chunk 32, 4-stage cp.async (wait_group 2), 8 warps.
// smem: As[4][128*40]h, Ws[4][128*40]h = 80KB.  B frags via ldmatrix.
// ---------------------------------------------------------------------------
__global__ __launch_bounds__(256, 2) void gemm_h(
    const __half* __restrict__ A, const __half* __restrict__ Wb,
    const __half* __restrict__ Add, const float* __restrict__ bias,
    __half* __restrict__ o0, __half* __restrict__ o1, __half* __restrict__ o2,
    int mode0, int mode1, int mode2)
{
    extern __shared__ char smc[];
    unsigned sa = (unsigned)__cvta_generic_to_shared(smc);
    unsigned sw = sa + 40960;          // 4 stages x 5120 halves x 2B
    int m0 = blockIdx.y * 128;
    int nmat = blockIdx.x >> 2;
    int ncol0 = (blockIdx.x & 3) * 128;
    const __half* Wp = Wb + (size_t)blockIdx.x * 128 * 512;
    __half* Cout; int mode;
    if (nmat == 0)      { Cout = o0; mode = mode0; }
    else if (nmat == 1) { Cout = o1; mode = mode1; }
    else                { Cout = o2; mode = mode2; }

    int tid = threadIdx.x;
    int w = tid >> 5, l = tid & 31;
    int g = l >> 2, t = l & 3;
    int wm = (w & 1) * 64, wn = (w >> 1) * 32;
    int u = tid & 3, r0 = tid >> 2;    // 16B chunk, row 0..63

    int p = l & 7, sel = l >> 3;
    unsigned a_off = (unsigned)(((wm + p + (sel & 1) * 8) * 40 + (sel >> 1) * 8) * 2);
    unsigned b_off = (unsigned)(((p + (sel & 1) * 8) * 40 + (sel >> 1) * 8) * 2);

    float c[4][4][4];
#pragma unroll
    for (int mi = 0; mi < 4; mi++)
#pragma unroll
        for (int ni = 0; ni < 4; ni++)
#pragma unroll
            for (int r = 0; r < 4; r++) c[mi][ni][r] = 0.f;

#define GH_LOAD(st, kc) do { \
    const __half* Ag = A  + (size_t)(m0 + r0) * 512 + (kc) * 32 + u * 8; \
    const __half* Wg = Wp + (size_t)r0 * 512 + (kc) * 32 + u * 8; \
    unsigned da = sa + (unsigned)((st) * 10240 + (r0 * 40 + u * 8) * 2); \
    unsigned dw = sw + (unsigned)((st) * 10240 + (r0 * 40 + u * 8) * 2); \
    CP16(da, Ag); CP16(da + 5120, Ag + (size_t)64 * 512); \
    CP16(dw, Wg); CP16(dw + 5120, Wg + (size_t)64 * 512); \
    CP_COMMIT(); } while (0)

    GH_LOAD(0, 0); GH_LOAD(1, 1); GH_LOAD(2, 2);
#pragma unroll 1
    for (int kt = 0; kt < 16; kt++) {
        int cur = kt & 3;
        CP_WAIT2();
        __syncthreads();
        if (kt < 13) { GH_LOAD((kt + 3) & 3, kt + 3); } else { CP_COMMIT(); }
        unsigned cb = (unsigned)(cur * 10240);
#pragma unroll
        for (int ks = 0; ks < 2; ks++) {
            unsigned kofs = (unsigned)(ks * 32);
            unsigned a[4][4];
#pragma unroll
            for (int mi = 0; mi < 4; mi++) {
                unsigned addr = sa + cb + a_off + (unsigned)(mi * 16 * 80) + kofs;
                LDSM_X4(a[mi][0], a[mi][1], a[mi][2], a[mi][3], addr);
            }
            unsigned b[4][2];
#pragma unroll
            for (int nj = 0; nj < 2; nj++) {
                unsigned addr = sw + cb + b_off + (unsigned)((wn + nj * 16) * 80) + kofs;
                unsigned q0, q1, q2, q3;
                LDSM_X4(q0, q1, q2, q3, addr);
                b[nj * 2][0] = q0;     b[nj * 2][1] = q2;
                b[nj * 2 + 1][0] = q1; b[nj * 2 + 1][1] = q3;
            }
#pragma unroll
            for (int mi = 0; mi < 4; mi++)
#pragma unroll
                for (int ni = 0; ni < 4; ni++)
                    MMA_F16(c[mi][ni][0], c[mi][ni][1], c[mi][ni][2], c[mi][ni][3],
                            a[mi][0], a[mi][1], a[mi][2], a[mi][3],
                            b[ni][0], b[ni][1]);
        }
    }
#undef GH_LOAD

#pragma unroll
    for (int mi = 0; mi < 4; mi++) {
#pragma unroll
        for (int ni = 0; ni < 4; ni++) {
            int m = m0 + wm + mi * 16 + g;
            int n = ncol0 + wn + ni * 8 + 2 * t;
            float v00 = c[mi][ni][0], v01 = c[mi][ni][1];
            float v10 = c[mi][ni][2], v11 = c[mi][ni][3];
            if (mode == 1) {
                float2 a0 = __half22float2(*(const __half2*)(Add + (size_t)m * 512 + n));
                float2 a1 = __half22float2(*(const __half2*)(Add + (size_t)(m + 8) * 512 + n));
                v00 += a0.x; v01 += a0.y; v10 += a1.x; v11 += a1.y;
            } else if (mode == 2) {
                float2 bb = *(const float2*)(bias + n);
                v00 += bb.x; v01 += bb.y; v10 += bb.x; v11 += bb.y;
            }
            *(__half2*)(Cout + (size_t)m * 512 + n) = __floats2half2_rn(v00, v01);
            *(__half2*)(Cout + (size_t)(m + 8) * 512 + n) = __floats2half2_rn(v10, v11);
        }
    }
}

// ---------------------------------------------------------------------------
// fp16 tensor-core attention: block per (n,head), 192 threads (6 warps),
// warp w owns q-rows [16w,16w+16). QK^T and PV via m16n8k16 fp16, fp32 accum.
// P stays in registers: QK C-fragment layout == PV A-fragment layout.
// ---------------------------------------------------------------------------
__global__ __launch_bounds__(192, 2) void attn_h(
    const __half* __restrict__ Qg, const __half* __restrict__ Kg,
    const __half* __restrict__ Vg, __half* __restrict__ Og)
{
    extern __shared__ char smc[];
    __half* Qh = (__half*)smc;          // [96][72]
    __half* Kh = Qh + 96 * 72;          // [96][72]
    __half* Vh = Kh + 96 * 72;          // [96][72]
    unsigned sq = (unsigned)__cvta_generic_to_shared(Qh);
    unsigned sk = (unsigned)__cvta_generic_to_shared(Kh);
    unsigned sv = (unsigned)__cvta_generic_to_shared(Vh);

    int hd = blockIdx.x, n = blockIdx.y;
    size_t base = (size_t)n * 96 * 512 + hd * 64;
    int tid = threadIdx.x;
    int w = tid >> 5, l = tid & 31;
    int g = l >> 2, t = l & 3;
    int qr = w * 16;
    int p = l & 7, sel = l >> 3;

    for (int i = tid; i < 96 * 8; i += 192) {
        int r = i >> 3, cc = (i & 7) * 8;
        uint4 q = *(const uint4*)(Qg + base + (size_t)r * 512 + cc);
        uint4 k = *(const uint4*)(Kg + base + (size_t)r * 512 + cc);
        uint4 v = *(const uint4*)(Vg + base + (size_t)r * 512 + cc);
        *(uint4*)(Qh + r * 72 + cc) = q;
        *(uint4*)(Kh + r * 72 + cc) = k;
        *(uint4*)(Vh + r * 72 + cc) = v;
    }
    __syncthreads();

    // ---- S = Q K^T : c[12][4] covers 16 q-rows x 96 kv-cols ----
    float c[12][4];
#pragma unroll
    for (int ni = 0; ni < 12; ni++)
#pragma unroll
        for (int r = 0; r < 4; r++) c[ni][r] = 0.f;

    unsigned aq_off = (unsigned)(((qr + p + (sel & 1) * 8) * 72 + (sel >> 1) * 8) * 2);
    unsigned bk_off = (unsigned)(((p + (sel & 1) * 8) * 72 + (sel >> 1) * 8) * 2);

#pragma unroll
    for (int ks = 0; ks < 4; ks++) {           // k = dh, 4 steps of 16
        unsigned kofs = (unsigned)(ks * 32);
        unsigned a0, a1, a2, a3;
        LDSM_X4(a0, a1, a2, a3, sq + aq_off + kofs);
#pragma unroll
        for (int nj = 0; nj < 6; nj++) {       // kv rows, 6 tiles of 16
            unsigned addr = sk + bk_off + (unsigned)(nj * 16 * 144) + kofs;
            unsigned q0, q1, q2, q3;
            LDSM_X4(q0, q1, q2, q3, addr);
            MMA_F16(c[2*nj][0], c[2*nj][1], c[2*nj][2], c[2*nj][3],
                    a0, a1, a2, a3, q0, q2);
            MMA_F16(c[2*nj+1][0], c[2*nj+1][1], c[2*nj+1][2], c[2*nj+1][3],
                    a0, a1, a2, a3, q1, q3);
        }
    }

    // ---- softmax over kv (rows qr+g and qr+g+8) ----
    float m0 = -1e30f, m1 = -1e30f;
#pragma unroll
    for (int ni = 0; ni < 12; ni++) {
#pragma unroll
        for (int r = 0; r < 4; r++) c[ni][r] *= 0.125f;
        m0 = fmaxf(m0, fmaxf(c[ni][0], c[ni][1]));
        m1 = fmaxf(m1, fmaxf(c[ni][2], c[ni][3]));
    }
    m0 = fmaxf(m0, __shfl_xor_sync(0xffffffff, m0, 1));
    m0 = fmaxf(m0, __shfl_xor_sync(0xffffffff, m0, 2));
    m1 = fmaxf(m1, __shfl_xor_sync(0xffffffff, m1, 1));
    m1 = fmaxf(m1, __shfl_xor_sync(0xffffffff, m1, 2));
    float s0 = 0.f, s1 = 0.f;
#pragma unroll
    for (int ni = 0; ni < 12; ni++) {
        c[ni][0] = fast_exp(c[ni][0] - m0);
        c[ni][1] = fast_exp(c[ni][1] - m0);
        c[ni][2] = fast_exp(c[ni][2] - m1);
        c[ni][3] = fast_exp(c[ni][3] - m1);
        s0 += c[ni][0] + c[ni][1];
        s1 += c[ni][2] + c[ni][3];
    }
    s0 += __shfl_xor_sync(0xffffffff, s0, 1);
    s0 += __shfl_xor_sync(0xffffffff, s0, 2);
    s1 += __shfl_xor_sync(0xffffffff, s1, 1);
    s1 += __shfl_xor_sync(0xffffffff, s1, 2);

    // ---- O = P V : P fragments straight from c (A-frag layout match) ----
    float o[8][4];
#pragma unroll
    for (int ni = 0; ni < 8; ni++)
#pragma unroll
        for (int r = 0; r < 4; r++) o[ni][r] = 0.f;

    unsigned bv_off = (unsigned)(((p + (sel & 1) * 8) * 72 + (sel >> 1) * 8) * 2);
#pragma unroll
    for (int ks = 0; ks < 6; ks++) {           // kv, 6 steps of 16
        unsigned a0 = h2pack(c[2*ks][0],   c[2*ks][1]);
        unsigned a1 = h2pack(c[2*ks][2],   c[2*ks][3]);
        unsigned a2 = h2pack(c[2*ks+1][0], c[2*ks+1][1]);
        unsigned a3 = h2pack(c[2*ks+1][2], c[2*ks+1][3]);
#pragma unroll
        for (int nj = 0; nj < 4; nj++) {       // dh cols, 4 tiles of 16
            unsigned addr = sv + bv_off + (unsigned)(ks * 16 * 144 + nj * 32);
            unsigned q0, q1, q2, q3;
            LDSM_X4T(q0, q1, q2, q3, addr);
            MMA_F16(o[2*nj][0], o[2*nj][1], o[2*nj][2], o[2*nj][3],
                    a0, a1, a2, a3, q0, q1);
            MMA_F16(o[2*nj+1][0], o[2*nj+1][1], o[2*nj+1][2], o[2*nj+1][3],
                    a0, a1, a2, a3, q2, q3);
        }
    }

    float inv0 = 1.0f / s0, inv1 = 1.0f / s1;
    __half* ob = Og + base;
#pragma unroll
    for (int ni = 0; ni < 8; ni++) {
        *(__half2*)(ob + (size_t)(qr + g) * 512 + ni * 8 + 2 * t) =
            __floats2half2_rn(o[ni][0] * inv0, o[ni][1] * inv0);
        *(__half2*)(ob + (size_t)(qr + g + 8) * 512 + ni * 8 + 2 * t) =
            __floats2half2_rn(o[ni][2] * inv1, o[ni][3] * inv1);
    }
}

// ---------------------------------------------------------------------------
__global__ void bnprep(const float* __restrict__ g, const float* __restrict__ b,
                       const float* __restrict__ m, const float* __restrict__ v) {
    int c = blockIdx.x * 256 + threadIdx.x;
    if (c < 512) {
        float sc = g[c] * rsqrtf(v[c] + 1e-5f);
        g_bnscale[c] = sc;
        g_bnbias[c]  = b[c] - m[c] * sc;
    }
}

__global__ void dwconv_bn(const float* __restrict__ x, const float* __restrict__ wd,
                          __half* __restrict__ o) {
    int idx = blockIdx.x * 256 + threadIdx.x;
    int w = idx % 96;
    int t = idx / 96;
    int h = t % 96;
    int bc = t / 96;
    int c = bc & 511;
    const float* wt = wd + c * 9;
    const float* xp = x + (size_t)bc * 9216;
    float s = 0.f;
#pragma unroll
    for (int kh = -1; kh <= 1; kh++) {
        int hh = h + kh;
        if (hh < 0 || hh >= 96) continue;
#pragma unroll
        for (int kw = -1; kw <= 1; kw++) {
            int ww = w + kw;
            if (ww < 0 || ww >= 96) continue;
            s = fmaf(xp[hh * 96 + ww], wt[(kh + 1) * 3 + (kw + 1)], s);
        }
    }
    o[idx] = __float2half_rn(fmaf(s, g_bnscale[c], g_bnbias[c]));
}

// ---------------------------------------------------------------------------
// fp16 1x1-conv GEMM per batch (2-stage, validated round 5): Out = clip(pw@y)+CR
// ---------------------------------------------------------------------------
__global__ __launch_bounds__(256, 2) void gemm_conv_h(
    const __half* __restrict__ Apw, const __half* __restrict__ Bt,
    const float* __restrict__ CR, float* __restrict__ Out)
{
    extern __shared__ char smc[];
    __half* As = (__half*)smc;
    __half* Bs = (__half*)(smc + 36864);
    int bat = blockIdx.z;
    size_t boff = (size_t)bat * 512 * 9216;
    const __half* Bg = Bt + boff;
    int n0 = blockIdx.x * 128;
    int m0 = blockIdx.y * 128;
    int tid = threadIdx.x;
    int w = tid >> 5, l = tid & 31;
    int g = l >> 2, t = l & 3;
    int wm = (w & 1) * 64, wn = (w >> 1) * 32;

    int uA = tid & 7, rA = tid >> 3;
    int uB = tid & 15, rB = tid >> 4;

    unsigned sa = (unsigned)__cvta_generic_to_shared(As);
    unsigned sb = (unsigned)__cvta_generic_to_shared(Bs);
    int p = l & 7, sel = l >> 3;
    unsigned a_off = (unsigned)(((wm + p + (sel & 1) * 8) * 72 + (sel >> 1) * 8) * 2);
    unsigned b_off = (unsigned)(((p + (sel & 1) * 8) * 136 + (sel >> 1) * 8) * 2);

    float c[4][4][4];
#pragma unroll
    for (int mi = 0; mi < 4; mi++)
#pragma unroll
        for (int ni = 0; ni < 4; ni++)
#pragma unroll
            for (int r = 0; r < 4; r++) c[mi][ni][r] = 0.f;

#define GC_LOAD(st, kc) do { \
    const __half* Ag = Apw + (size_t)(m0 + rA) * 512 + (kc) * 64 + uA * 8; \
    unsigned da = sa + (unsigned)(((st) * 9216 + rA * 72 + uA * 8) * 2); \
    _Pragma("unroll") \
    for (int i = 0; i < 4; i++) \
        CP16(da + (unsigned)(i * 32 * 144), Ag + (size_t)i * 32 * 512); \
    const __half* Bgp = Bg + (size_t)((kc) * 64 + rB) * 9216 + n0 + uB * 8; \
    unsigned db = sb + (unsigned)(((st) * 8704 + rB * 136 + uB * 8) * 2); \
    _Pragma("unroll") \
    for (int i = 0; i < 4; i++) \
        CP16(db + (unsigned)(i * 16 * 272), Bgp + (size_t)i * 16 * 9216); \
    CP_COMMIT(); } while (0)

    GC_LOAD(0, 0);
#pragma unroll 1
    for (int kt = 0; kt < 8; kt++) {
        int cur = kt & 1;
        CP_WAIT0();
        __syncthreads();
        if (kt < 7) GC_LOAD(cur ^ 1, kt + 1);
        unsigned abase = sa + (unsigned)(cur * 9216 * 2) + a_off;
        unsigned bbase = sb + (unsigned)(cur * 8704 * 2) + b_off;
#pragma unroll
        for (int ks = 0; ks < 4; ks++) {
            int k0 = ks * 16;
            unsigned a[4][4];
#pragma unroll
            for (int mi = 0; mi < 4; mi++) {
                unsigned addr = abase + (unsigned)((mi * 16 * 72 + k0) * 2);
                LDSM_X4(a[mi][0], a[mi][1], a[mi][2], a[mi][3], addr);
            }
            unsigned b[4][2];
#pragma unroll
            for (int nj = 0; nj < 2; nj++) {
                unsigned addr = bbase + (unsigned)((k0 * 136 + wn + nj * 16) * 2);
                unsigned q0, q1, q2, q3;
                LDSM_X4T(q0, q1, q2, q3, addr);
                b[nj * 2][0] = q0;     b[nj * 2][1] = q1;
                b[nj * 2 + 1][0] = q2; b[nj * 2 + 1][1] = q3;
            }
#pragma unroll
            for (int mi = 0; mi < 4; mi++)
#pragma unroll
                for (int ni = 0; ni < 4; ni++)
                    MMA_F16(c[mi][ni][0], c[mi][ni][1], c[mi][ni][2], c[mi][ni][3],
                            a[mi][0], a[mi][1], a[mi][2], a[mi][3],
                            b[ni][0], b[ni][1]);
        }
        __syncthreads();
    }
#undef GC_LOAD

#pragma unroll
    for (int mi = 0; mi < 4; mi++) {
#pragma unroll
        for (int ni = 0; ni < 4; ni++) {
            int m = m0 + wm + mi * 16 + g;
            int n = n0 + wn + ni * 8 + 2 * t;
            size_t off0 = boff + (size_t)m * 9216 + n;
            size_t off1 = boff + (size_t)(m + 8) * 9216 + n;
            float2 cr0 = *(const float2*)(CR + off0);
            float2 cr1 = *(const float2*)(CR + off1);
            float2 o0, o1;
            o0.x = fminf(fmaxf(c[mi][ni][0], 0.f), 6.f) + cr0.x;
            o0.y = fminf(fmaxf(c[mi][ni][1], 0.f), 6.f) + cr0.y;
            o1.x = fminf(fmaxf(c[mi][ni][2], 0.f), 6.f) + cr1.x;
            o1.y = fminf(fmaxf(c[mi][ni][3], 0.f), 6.f) + cr1.y;
            *(float2*)(Out + off0) = o0;
            *(float2*)(Out + off1) = o1;
        }
    }
}

// ---------------------------------------------------------------------------
// Host launch
// ---------------------------------------------------------------------------
extern "C" void kernel_launch(void* const* d_in, const int* in_sizes, int n_in,
                              void* d_out, int out_size) {
    const float* x   = (const float*)d_in[0];
    const float* Wk  = (const float*)d_in[1];
    const float* Wv  = (const float*)d_in[2];
    const float* Wo  = (const float*)d_in[3];
    const float* cWq = (const float*)d_in[4];
    const float* cbq = (const float*)d_in[5];
    const float* cWv = (const float*)d_in[6];
    const float* cWo = (const float*)d_in[7];
    const float* dww = (const float*)d_in[8];
    const float* bng = (const float*)d_in[9];
    const float* bnb = (const float*)d_in[10];
    const float* bnm = (const float*)d_in[11];
    const float* bnv = (const float*)d_in[12];
    const float* pww = (const float*)d_in[13];
    float* out = (float*)d_out;

    __half* hb = nullptr;
    cudaGetSymbolAddress((void**)&hb, g_hb);
    __half* h0 = hb + (size_t)0 * TOTE;
    __half* h1 = hb + (size_t)1 * TOTE;
    __half* h2 = hb + (size_t)2 * TOTE;
    __half* h3 = hb + (size_t)3 * TOTE;
    __half* h4 = hb + (size_t)4 * TOTE;
    float* crf = nullptr;
    cudaGetSymbolAddress((void**)&crf, g_crf);
    __half* wh = nullptr;
    cudaGetSymbolAddress((void**)&wh, g_wh);
    // slot order: 0=Wk, 1=Wv, 2=cWv, 3=Wo, 4=cWq, 5=cWo, 6=pw
    __half* wKVV = wh;                              // slots 0..2 contiguous
    __half* rWo  = wh + (size_t)3 * 262144;
    __half* rcWq = wh + (size_t)4 * 262144;
    __half* rcWo = wh + (size_t)5 * 262144;
    __half* rpw  = wh + (size_t)6 * 262144;

    const int GEMM_SMEM = 8 * 5120 * 2;             // 81920
    const int CONV_SMEM = (2 * 9216 + 2 * 8704) * 2;
    const int ATTN_SMEM = 3 * 96 * 72 * 2;          // 41472
    cudaFuncSetAttribute(gemm_h, cudaFuncAttributeMaxDynamicSharedMemorySize, GEMM_SMEM);
    cudaFuncSetAttribute(gemm_conv_h, cudaFuncAttributeMaxDynamicSharedMemorySize, CONV_SMEM);
    cudaFuncSetAttribute(attn_h, cudaFuncAttributeMaxDynamicSharedMemorySize, ATTN_SMEM);

    dim3 tb(32, 8);
    dim3 tg(3, 16, 768);

    wprep<<<1792, 256>>>(Wk, Wv, cWv, Wo, cWq, cWo, pww);
    img2seq<<<tg, tb>>>(x, h0);
    // fused: k = h0@Wk^T + h0 -> h1 ; v = h0@Wv^T -> h2 ; kv = h0@cWv^T -> h3
    gemm_h<<<dim3(12, 576), 256, GEMM_SMEM>>>(h0, wKVV, h0, nullptr, h1, h2, h3, 1, 0, 0);
    attn_h<<<dim3(8, 768), 192, ATTN_SMEM>>>(h0, h1, h2, h4);
    gemm_h<<<dim3(4, 576), 256, GEMM_SMEM>>>(h4, rWo, nullptr, nullptr, h1, h1, h1, 0, 0, 0);
    seq2img_hh<<<tg, tb>>>(h1, h2);
    gemm_h<<<dim3(4, 576), 256, GEMM_SMEM>>>(h2, rcWq, nullptr, cbq, h4, h4, h4, 2, 2, 2);
    attn_h<<<dim3(8, 768), 192, ATTN_SMEM>>>(h4, h3, h3, h1);
    gemm_h<<<dim3(4, 576), 256, GEMM_SMEM>>>(h1, rcWo, nullptr, nullptr, h2, h2, h2, 0, 0, 0);
    seq2img_hf<<<tg, tb>>>(h2, crf);
    bnprep<<<2, 256>>>(bng, bnb, bnm, bnv);
    dwconv_bn<<<147456, 256>>>(x, dww, h0);
    gemm_conv_h<<<dim3(72, 4, 8), 256, CONV_SMEM>>>(rpw, h0, crf, out);
}

// round 8
// speedup vs baseline: 5.1728x; 1.1184x over previous
#include <cuda_runtime.h>
#include <cuda_fp16.h>
#include <math.h>
#include <cstdint>

// ---------------------------------------------------------------------------
// Problem constants: B=8, C=512, H=W=96, heads=8, dh=64
// seq layout: [768, 96, 512]  (n = b*96 + w, t = h, channel c)
// ---------------------------------------------------------------------------
#define TOTE 37748736  // 768*96*512

__device__ __half g_hb[5][TOTE];     // fp16 activation buffers
__device__ float  g_crf[TOTE];       // cross-attn output (fp32 for final add)
__device__ __half g_wh[7 * 262144];  // fp16 weights, slot order: Wk,Wv,cWv,Wo,cWq,cWo,pw
__device__ float  g_bnscale[512];
__device__ float  g_bnbias[512];

__device__ __forceinline__ float fast_exp(float x) {
    x = fmaxf(x, -87.0f);
    float t = x * 1.44269504088896f;
    float fi = floorf(t);
    float f = t - fi;
    float p = 1.54035304e-4f;
    p = fmaf(p, f, 1.33335581e-3f);
    p = fmaf(p, f, 9.61812910e-3f);
    p = fmaf(p, f, 5.55041087e-2f);
    p = fmaf(p, f, 2.40226507e-1f);
    p = fmaf(p, f, 6.93147181e-1f);
    p = fmaf(p, f, 1.0f);
    return p * __int_as_float(((int)fi + 127) << 23);
}

#define MMA_F16(c0,c1,c2,c3,a0,a1,a2,a3,b0,b1) \
    asm volatile("mma.sync.aligned.m16n8k16.row.col.f32.f16.f16.f32 " \
                 "{%0,%1,%2,%3},{%4,%5,%6,%7},{%8,%9},{%0,%1,%2,%3};" \
                 : "+f"(c0),"+f"(c1),"+f"(c2),"+f"(c3) \
                 : "r"(a0),"r"(a1),"r"(a2),"r"(a3),"r"(b0),"r"(b1))

#define LDSM_X4(r0,r1,r2,r3,addr) \
    asm volatile("ldmatrix.sync.aligned.m8n8.x4.shared.b16 {%0,%1,%2,%3}, [%4];" \
                 : "=r"(r0),"=r"(r1),"=r"(r2),"=r"(r3) : "r"(addr))

#define LDSM_X4T(r0,r1,r2,r3,addr) \
    asm volatile("ldmatrix.sync.aligned.m8n8.x4.trans.shared.b16 {%0,%1,%2,%3}, [%4];" \
                 : "=r"(r0),"=r"(r1),"=r"(r2),"=r"(r3) : "r"(addr))

#define CP16(dst, src) \
    asm volatile("cp.async.cg.shared.global [%0], [%1], 16;" :: "r"(dst), "l"(src))
#define CP_COMMIT() asm volatile("cp.async.commit_group;")
#define CP_WAIT0()  asm volatile("cp.async.wait_group 0;")
#define CP_WAIT2()  asm volatile("cp.async.wait_group 2;")

__device__ __forceinline__ unsigned h2pack(float a, float b) {
    unsigned r;
    asm("cvt.rn.f16x2.f32 %0, %2, %1;" : "=r"(r) : "f"(a), "f"(b));
    return r;
}

// ---------------------------------------------------------------------------
// Weight prep: fp16-round 7 [512x512] matrices into g_wh (slot order = arg order)
// ---------------------------------------------------------------------------
__global__ void wprep(const float* __restrict__ a0, const float* __restrict__ a1,
                      const float* __restrict__ a2, const float* __restrict__ a3,
                      const float* __restrict__ a4, const float* __restrict__ a5,
                      const float* __restrict__ a6) {
    int i = blockIdx.x * 256 + threadIdx.x;
    int mat = i >> 16;
    int off = (i & 65535) * 4;
    const float* s;
    switch (mat) {
        case 0: s = a0; break; case 1: s = a1; break; case 2: s = a2; break;
        case 3: s = a3; break; case 4: s = a4; break; case 5: s = a5; break;
        default: s = a6; break;
    }
    float4 v = *(const float4*)(s + off);
    *(__half2*)(g_wh + (size_t)mat * 262144 + off)     = __floats2half2_rn(v.x, v.y);
    *(__half2*)(g_wh + (size_t)mat * 262144 + off + 2) = __floats2half2_rn(v.z, v.w);
}

// ---------------------------------------------------------------------------
// Layout transposes (c <-> w per (b,h) plane)
// ---------------------------------------------------------------------------
__global__ void img2seq(const float* __restrict__ img, __half* __restrict__ seq) {
    __shared__ float tile[32][33];
    int bh = blockIdx.z;
    int b = bh / 96, h = bh % 96;
    int c0 = blockIdx.y * 32, w0 = blockIdx.x * 32;
    int tx = threadIdx.x, ty = threadIdx.y;
#pragma unroll
    for (int i = 0; i < 4; i++) {
        int c = c0 + ty + i * 8;
        tile[ty + i * 8][tx] = img[(((size_t)b * 512 + c) * 96 + h) * 96 + w0 + tx];
    }
    __syncthreads();
#pragma unroll
    for (int i = 0; i < 4; i++) {
        int w = w0 + ty + i * 8;
        seq[(((size_t)(b * 96 + w)) * 96 + h) * 512 + c0 + tx] =
            __float2half_rn(tile[tx][ty + i * 8]);
    }
}

__global__ void seq2img_hh(const __half* __restrict__ seq, __half* __restrict__ img) {
    __shared__ __half tile[32][33];
    int bh = blockIdx.z;
    int b = bh / 96, h = bh % 96;
    int c0 = blockIdx.y * 32, w0 = blockIdx.x * 32;
    int tx = threadIdx.x, ty = threadIdx.y;
#pragma unroll
    for (int i = 0; i < 4; i++) {
        int w = w0 + ty + i * 8;
        tile[ty + i * 8][tx] = seq[(((size_t)(b * 96 + w)) * 96 + h) * 512 + c0 + tx];
    }
    __syncthreads();
#pragma unroll
    for (int i = 0; i < 4; i++) {
        int c = c0 + ty + i * 8;
        img[(((size_t)b * 512 + c) * 96 + h) * 96 + w0 + tx] = tile[tx][ty + i * 8];
    }
}

__global__ void seq2img_hf(const __half* __restrict__ seq, float* __restrict__ img) {
    __shared__ float tile[32][33];
    int bh = blockIdx.z;
    int b = bh / 96, h = bh % 96;
    int c0 = blockIdx.y * 32, w0 = blockIdx.x * 32;
    int tx = threadIdx.x, ty = threadIdx.y;
#pragma unroll
    for (int i = 0; i < 4; i++) {
        int w = w0 + ty + i * 8;
        tile[ty + i * 8][tx] =
            __half2float(seq[(((size_t)(b * 96 + w)) * 96 + h) * 512 + c0 + tx]);
    }
    __syncthreads();
#pragma unroll
    for (int i = 0; i < 4; i++) {
        int c = c0 + ty + i * 8;
        img[(((size_t)b * 512 + c) * 96 + h) * 96 + w0 + tx] = tile[tx][ty + i * 8];
    }
}

// ---------------------------------------------------------------------------
// fp16 GEMM, multi-output (unchanged from round 7, passing).
// ---------------------------------------------------------------------------
__global__ __launch_bounds__(256, 2) void gemm_h(
    const __half* __restrict__ A, const __half* __restrict__ Wb,
    const __half* __restrict__ Add, const float* __restrict__ bias,
    __half* __restrict__ o0, __half* __restrict__ o1, __half* __restrict__ o2,
    int mode0, int mode1, int mode2)
{
    extern __shared__ char smc[];
    unsigned sa = (unsigned)__cvta_generic_to_shared(smc);
    unsigned sw = sa + 40960;          // 4 stages x 5120 halves x 2B
    int m0 = blockIdx.y * 128;
    int nmat = blockIdx.x >> 2;
    int ncol0 = (blockIdx.x & 3) * 128;
    const __half* Wp = Wb + (size_t)blockIdx.x * 128 * 512;
    __half* Cout; int mode;
    if (nmat == 0)      { Cout = o0; mode = mode0; }
    else if (nmat == 1) { Cout = o1; mode = mode1; }
    else                { Cout = o2; mode = mode2; }

    int tid = threadIdx.x;
    int w = tid >> 5, l = tid & 31;
    int g = l >> 2, t = l & 3;
    int wm = (w & 1) * 64, wn = (w >> 1) * 32;
    int u = tid & 3, r0 = tid >> 2;    // 16B chunk, row 0..63

    int p = l & 7, sel = l >> 3;
    unsigned a_off = (unsigned)(((wm + p + (sel & 1) * 8) * 40 + (sel >> 1) * 8) * 2);
    unsigned b_off = (unsigned)(((p + (sel & 1) * 8) * 40 + (sel >> 1) * 8) * 2);

    float c[4][4][4];
#pragma unroll
    for (int mi = 0; mi < 4; mi++)
#pragma unroll
        for (int ni = 0; ni < 4; ni++)
#pragma unroll
            for (int r = 0; r < 4; r++) c[mi][ni][r] = 0.f;

#define GH_LOAD(st, kc) do { \
    const __half* Ag = A  + (size_t)(m0 + r0) * 512 + (kc) * 32 + u * 8; \
    const __half* Wg = Wp + (size_t)r0 * 512 + (kc) * 32 + u * 8; \
    unsigned da = sa + (unsigned)((st) * 10240 + (r0 * 40 + u * 8) * 2); \
    unsigned dw = sw + (unsigned)((st) * 10240 + (r0 * 40 + u * 8) * 2); \
    CP16(da, Ag); CP16(da + 5120, Ag + (size_t)64 * 512); \
    CP16(dw, Wg); CP16(dw + 5120, Wg + (size_t)64 * 512); \
    CP_COMMIT(); } while (0)

    GH_LOAD(0, 0); GH_LOAD(1, 1); GH_LOAD(2, 2);
#pragma unroll 1
    for (int kt = 0; kt < 16; kt++) {
        int cur = kt & 3;
        CP_WAIT2();
        __syncthreads();
        if (kt < 13) { GH_LOAD((kt + 3) & 3, kt + 3); } else { CP_COMMIT(); }
        unsigned cb = (unsigned)(cur * 10240);
#pragma unroll
        for (int ks = 0; ks < 2; ks++) {
            unsigned kofs = (unsigned)(ks * 32);
            unsigned a[4][4];
#pragma unroll
            for (int mi = 0; mi < 4; mi++) {
                unsigned addr = sa + cb + a_off + (unsigned)(mi * 16 * 80) + kofs;
                LDSM_X4(a[mi][0], a[mi][1], a[mi][2], a[mi][3], addr);
            }
            unsigned b[4][2];
#pragma unroll
            for (int nj = 0; nj < 2; nj++) {
                unsigned addr = sw + cb + b_off + (unsigned)((wn + nj * 16) * 80) + kofs;
                unsigned q0, q1, q2, q3;
                LDSM_X4(q0, q1, q2, q3, addr);
                b[nj * 2][0] = q0;     b[nj * 2][1] = q2;
                b[nj * 2 + 1][0] = q1; b[nj * 2 + 1][1] = q3;
            }
#pragma unroll
            for (int mi = 0; mi < 4; mi++)
#pragma unroll
                for (int ni = 0; ni < 4; ni++)
                    MMA_F16(c[mi][ni][0], c[mi][ni][1], c[mi][ni][2], c[mi][ni][3],
                            a[mi][0], a[mi][1], a[mi][2], a[mi][3],
                            b[ni][0], b[ni][1]);
        }
    }
#undef GH_LOAD

#pragma unroll
    for (int mi = 0; mi < 4; mi++) {
#pragma unroll
        for (int ni = 0; ni < 4; ni++) {
            int m = m0 + wm + mi * 16 + g;
            int n = ncol0 + wn + ni * 8 + 2 * t;
            float v00 = c[mi][ni][0], v01 = c[mi][ni][1];
            float v10 = c[mi][ni][2], v11 = c[mi][ni][3];
            if (mode == 1) {
                float2 a0 = __half22float2(*(const __half2*)(Add + (size_t)m * 512 + n));
                float2 a1 = __half22float2(*(const __half2*)(Add + (size_t)(m + 8) * 512 + n));
                v00 += a0.x; v01 += a0.y; v10 += a1.x; v11 += a1.y;
            } else if (mode == 2) {
                float2 bb = *(const float2*)(bias + n);
                v00 += bb.x; v01 += bb.y; v10 += bb.x; v11 += bb.y;
            }
            *(__half2*)(Cout + (size_t)m * 512 + n) = __floats2half2_rn(v00, v01);
            *(__half2*)(Cout + (size_t)(m + 8) * 512 + n) = __floats2half2_rn(v10, v11);
        }
    }
}

// ---------------------------------------------------------------------------
// fp16 tensor-core attention: block per (n,head), 192 threads (6 warps).
// P pre-packed into 24 regs before PV so the 48-reg fp32 S dies early;
// launch_bounds(192,3) caps regs at 112 -> 3 CTAs/SM.
// ---------------------------------------------------------------------------
__global__ __launch_bounds__(192, 3) void attn_h(
    const __half* __restrict__ Qg, const __half* __restrict__ Kg,
    const __half* __restrict__ Vg, __half* __restrict__ Og)
{
    extern __shared__ char smc[];
    __half* Qh = (__half*)smc;          // [96][72]
    __half* Kh = Qh + 96 * 72;          // [96][72]
    __half* Vh = Kh + 96 * 72;          // [96][72]
    unsigned sq = (unsigned)__cvta_generic_to_shared(Qh);
    unsigned sk = (unsigned)__cvta_generic_to_shared(Kh);
    unsigned sv = (unsigned)__cvta_generic_to_shared(Vh);

    int hd = blockIdx.x, n = blockIdx.y;
    size_t base = (size_t)n * 96 * 512 + hd * 64;
    int tid = threadIdx.x;
    int w = tid >> 5, l = tid & 31;
    int g = l >> 2, t = l & 3;
    int qr = w * 16;
    int p = l & 7, sel = l >> 3;

    for (int i = tid; i < 96 * 8; i += 192) {
        int r = i >> 3, cc = (i & 7) * 8;
        uint4 q = *(const uint4*)(Qg + base + (size_t)r * 512 + cc);
        uint4 k = *(const uint4*)(Kg + base + (size_t)r * 512 + cc);
        uint4 v = *(const uint4*)(Vg + base + (size_t)r * 512 + cc);
        *(uint4*)(Qh + r * 72 + cc) = q;
        *(uint4*)(Kh + r * 72 + cc) = k;
        *(uint4*)(Vh + r * 72 + cc) = v;
    }
    __syncthreads();

    // ---- S = Q K^T : c[12][4] covers 16 q-rows x 96 kv-cols ----
    float c[12][4];
#pragma unroll
    for (int ni = 0; ni < 12; ni++)
#pragma unroll
        for (int r = 0; r < 4; r++) c[ni][r] = 0.f;

    unsigned aq_off = (unsigned)(((qr + p + (sel & 1) * 8) * 72 + (sel >> 1) * 8) * 2);
    unsigned bk_off = (unsigned)(((p + (sel & 1) * 8) * 72 + (sel >> 1) * 8) * 2);

#pragma unroll
    for (int ks = 0; ks < 4; ks++) {           // k = dh, 4 steps of 16
        unsigned kofs = (unsigned)(ks * 32);
        unsigned a0, a1, a2, a3;
        LDSM_X4(a0, a1, a2, a3, sq + aq_off + kofs);
#pragma unroll
        for (int nj = 0; nj < 6; nj++) {       // kv rows, 6 tiles of 16
            unsigned addr = sk + bk_off + (unsigned)(nj * 16 * 144) + kofs;
            unsigned q0, q1, q2, q3;
            LDSM_X4(q0, q1, q2, q3, addr);
            MMA_F16(c[2*nj][0], c[2*nj][1], c[2*nj][2], c[2*nj][3],
                    a0, a1, a2, a3, q0, q2);
            MMA_F16(c[2*nj+1][0], c[2*nj+1][1], c[2*nj+1][2], c[2*nj+1][3],
                    a0, a1, a2, a3, q1, q3);
        }
    }

    // ---- softmax over kv (rows qr+g and qr+g+8) ----
    float m0 = -1e30f, m1 = -1e30f;
#pragma unroll
    for (int ni = 0; ni < 12; ni++) {
#pragma unroll
        for (int r = 0; r < 4; r++) c[ni][r] *= 0.125f;
        m0 = fmaxf(m0, fmaxf(c[ni][0], c[ni][1]));
        m1 = fmaxf(m1, fmaxf(c[ni][2], c[ni][3]));
    }
    m0 = fmaxf(m0, __shfl_xor_sync(0xffffffff, m0, 1));
    m0 = fmaxf(m0, __shfl_xor_sync(0xffffffff, m0, 2));
    m1 = fmaxf(m1, __shfl_xor_sync(0xffffffff, m1, 1));
    m1 = fmaxf(m1, __shfl_xor_sync(0xffffffff, m1, 2));
    float s0 = 0.f, s1 = 0.f;
#pragma unroll
    for (int ni = 0; ni < 12; ni++) {
        c[ni][0] = fast_exp(c[ni][0] - m0);
        c[ni][1] = fast_exp(c[ni][1] - m0);
        c[ni][2] = fast_exp(c[ni][2] - m1);
        c[ni][3] = fast_exp(c[ni][3] - m1);
        s0 += c[ni][0] + c[ni][1];
        s1 += c[ni][2] + c[ni][3];
    }
    s0 += __shfl_xor_sync(0xffffffff, s0, 1);
    s0 += __shfl_xor_sync(0xffffffff, s0, 2);
    s1 += __shfl_xor_sync(0xffffffff, s1, 1);
    s1 += __shfl_xor_sync(0xffffffff, s1, 2);

    // ---- pack ALL of P now; c dies here, freeing 48 regs ----
    unsigned ph[24];
#pragma unroll
    for (int ni = 0; ni < 12; ni++) {
        ph[2 * ni]     = h2pack(c[ni][0], c[ni][1]);
        ph[2 * ni + 1] = h2pack(c[ni][2], c[ni][3]);
    }

    // ---- O = P V ----
    float o[8][4];
#pragma unroll
    for (int ni = 0; ni < 8; ni++)
#pragma unroll
        for (int r = 0; r < 4; r++) o[ni][r] = 0.f;

    unsigned bv_off = (unsigned)(((p + (sel & 1) * 8) * 72 + (sel >> 1) * 8) * 2);
#pragma unroll
    for (int ks = 0; ks < 6; ks++) {           // kv, 6 steps of 16
        unsigned a0 = ph[4 * ks + 0];
        unsigned a1 = ph[4 * ks + 1];
        unsigned a2 = ph[4 * ks + 2];
        unsigned a3 = ph[4 * ks + 3];
#pragma unroll
        for (int nj = 0; nj < 4; nj++) {       // dh cols, 4 tiles of 16
            unsigned addr = sv + bv_off + (unsigned)(ks * 16 * 144 + nj * 32);
            unsigned q0, q1, q2, q3;
            LDSM_X4T(q0, q1, q2, q3, addr);
            MMA_F16(o[2*nj][0], o[2*nj][1], o[2*nj][2], o[2*nj][3],
                    a0, a1, a2, a3, q0, q1);
            MMA_F16(o[2*nj+1][0], o[2*nj+1][1], o[2*nj+1][2], o[2*nj+1][3],
                    a0, a1, a2, a3, q2, q3);
        }
    }

    float inv0 = 1.0f / s0, inv1 = 1.0f / s1;
    __half* ob = Og + base;
#pragma unroll
    for (int ni = 0; ni < 8; ni++) {
        *(__half2*)(ob + (size_t)(qr + g) * 512 + ni * 8 + 2 * t) =
            __floats2half2_rn(o[ni][0] * inv0, o[ni][1] * inv0);
        *(__half2*)(ob + (size_t)(qr + g + 8) * 512 + ni * 8 + 2 * t) =
            __floats2half2_rn(o[ni][2] * inv1, o[ni][3] * inv1);
    }
}

// ---------------------------------------------------------------------------
__global__ void bnprep(const float* __restrict__ g, const float* __restrict__ b,
                       const float* __restrict__ m, const float* __restrict__ v) {
    int c = blockIdx.x * 256 + threadIdx.x;
    if (c < 512) {
        float sc = g[c] * rsqrtf(v[c] + 1e-5f);
        g_bnscale[c] = sc;
        g_bnbias[c]  = b[c] - m[c] * sc;
    }
}

// depthwise 3x3 + BN, 4 outputs per thread along w (float4 row loads)
__global__ void dwconv_bn(const float* __restrict__ x, const float* __restrict__ wd,
                          __half* __restrict__ o) {
    int idx = blockIdx.x * 256 + threadIdx.x;   // 8*512*96*24 threads
    int wg = idx % 24;
    int t = idx / 24;
    int h = t % 96;
    int bc = t / 96;
    int c = bc & 511;
    int w0 = wg * 4;
    const float* wt = wd + c * 9;
    const float* xp = x + (size_t)bc * 9216;
    float acc[4] = {0.f, 0.f, 0.f, 0.f};
#pragma unroll
    for (int kh = 0; kh < 3; kh++) {
        int hh = h + kh - 1;
        if (hh < 0 || hh >= 96) continue;
        const float* row = xp + hh * 96;
        float4 v = *(const float4*)(row + w0);
        float left  = (w0 > 0)  ? row[w0 - 1] : 0.f;
        float right = (w0 < 92) ? row[w0 + 4] : 0.f;
        float vals[6] = {left, v.x, v.y, v.z, v.w, right};
        float wa = wt[kh * 3 + 0], wb = wt[kh * 3 + 1], wc = wt[kh * 3 + 2];
#pragma unroll
        for (int j = 0; j < 4; j++)
            acc[j] = fmaf(vals[j], wa, fmaf(vals[j + 1], wb, fmaf(vals[j + 2], wc, acc[j])));
    }
    float sc = g_bnscale[c], bb = g_bnbias[c];
    __half* op = o + (size_t)bc * 9216 + h * 96 + w0;
    *(__half2*)op       = __floats2half2_rn(fmaf(acc[0], sc, bb), fmaf(acc[1], sc, bb));
    *(__half2*)(op + 2) = __floats2half2_rn(fmaf(acc[2], sc, bb), fmaf(acc[3], sc, bb));
}

// ---------------------------------------------------------------------------
// fp16 1x1-conv GEMM per batch (unchanged, passing): Out = clip(pw@y)+CR
// ---------------------------------------------------------------------------
__global__ __launch_bounds__(256, 2) void gemm_conv_h(
    const __half* __restrict__ Apw, const __half* __restrict__ Bt,
    const float* __restrict__ CR, float* __restrict__ Out)
{
    extern __shared__ char smc[];
    __half* As = (__half*)smc;
    __half* Bs = (__half*)(smc + 36864);
    int bat = blockIdx.z;
    size_t boff = (size_t)bat * 512 * 9216;
    const __half* Bg = Bt + boff;
    int n0 = blockIdx.x * 128;
    int m0 = blockIdx.y * 128;
    int tid = threadIdx.x;
    int w = tid >> 5, l = tid & 31;
    int g = l >> 2, t = l & 3;
    int wm = (w & 1) * 64, wn = (w >> 1) * 32;

    int uA = tid & 7, rA = tid >> 3;
    int uB = tid & 15, rB = tid >> 4;

    unsigned sa = (unsigned)__cvta_generic_to_shared(As);
    unsigned sb = (unsigned)__cvta_generic_to_shared(Bs);
    int p = l & 7, sel = l >> 3;
    unsigned a_off = (unsigned)(((wm + p + (sel & 1) * 8) * 72 + (sel >> 1) * 8) * 2);
    unsigned b_off = (unsigned)(((p + (sel & 1) * 8) * 136 + (sel >> 1) * 8) * 2);

    float c[4][4][4];
#pragma unroll
    for (int mi = 0; mi < 4; mi++)
#pragma unroll
        for (int ni = 0; ni < 4; ni++)
#pragma unroll
            for (int r = 0; r < 4; r++) c[mi][ni][r] = 0.f;

#define GC_LOAD(st, kc) do { \
    const __half* Ag = Apw + (size_t)(m0 + rA) * 512 + (kc) * 64 + uA * 8; \
    unsigned da = sa + (unsigned)(((st) * 9216 + rA * 72 + uA * 8) * 2); \
    _Pragma("unroll") \
    for (int i = 0; i < 4; i++) \
        CP16(da + (unsigned)(i * 32 * 144), Ag + (size_t)i * 32 * 512); \
    const __half* Bgp = Bg + (size_t)((kc) * 64 + rB) * 9216 + n0 + uB * 8; \
    unsigned db = sb + (unsigned)(((st) * 8704 + rB * 136 + uB * 8) * 2); \
    _Pragma("unroll") \
    for (int i = 0; i < 4; i++) \
        CP16(db + (unsigned)(i * 16 * 272), Bgp + (size_t)i * 16 * 9216); \
    CP_COMMIT(); } while (0)

    GC_LOAD(0, 0);
#pragma unroll 1
    for (int kt = 0; kt < 8; kt++) {
        int cur = kt & 1;
        CP_WAIT0();
        __syncthreads();
        if (kt < 7) GC_LOAD(cur ^ 1, kt + 1);
        unsigned abase = sa + (unsigned)(cur * 9216 * 2) + a_off;
        unsigned bbase = sb + (unsigned)(cur * 8704 * 2) + b_off;
#pragma unroll
        for (int ks = 0; ks < 4; ks++) {
            int k0 = ks * 16;
            unsigned a[4][4];
#pragma unroll
            for (int mi = 0; mi < 4; mi++) {
                unsigned addr = abase + (unsigned)((mi * 16 * 72 + k0) * 2);
                LDSM_X4(a[mi][0], a[mi][1], a[mi][2], a[mi][3], addr);
            }
            unsigned b[4][2];
#pragma unroll
            for (int nj = 0; nj < 2; nj++) {
                unsigned addr = bbase + (unsigned)((k0 * 136 + wn + nj * 16) * 2);
                unsigned q0, q1, q2, q3;
                LDSM_X4T(q0, q1, q2, q3, addr);
                b[nj * 2][0] = q0;     b[nj * 2][1] = q1;
                b[nj * 2 + 1][0] = q2; b[nj * 2 + 1][1] = q3;
            }
#pragma unroll
            for (int mi = 0; mi < 4; mi++)
#pragma unroll
                for (int ni = 0; ni < 4; ni++)
                    MMA_F16(c[mi][ni][0], c[mi][ni][1], c[mi][ni][2], c[mi][ni][3],
                            a[mi][0], a[mi][1], a[mi][2], a[mi][3],
                            b[ni][0], b[ni][1]);
        }
        __syncthreads();
    }
#undef GC_LOAD

#pragma unroll
    for (int mi = 0; mi < 4; mi++) {
#pragma unroll
        for (int ni = 0; ni < 4; ni++) {
            int m = m0 + wm + mi * 16 + g;
            int n = n0 + wn + ni * 8 + 2 * t;
            size_t off0 = boff + (size_t)m * 9216 + n;
            size_t off1 = boff + (size_t)(m + 8) * 9216 + n;
            float2 cr0 = *(const float2*)(CR + off0);
            float2 cr1 = *(const float2*)(CR + off1);
            float2 o0, o1;
            o0.x = fminf(fmaxf(c[mi][ni][0], 0.f), 6.f) + cr0.x;
            o0.y = fminf(fmaxf(c[mi][ni][1], 0.f), 6.f) + cr0.y;
            o1.x = fminf(fmaxf(c[mi][ni][2], 0.f), 6.f) + cr1.x;
            o1.y = fminf(fmaxf(c[mi][ni][3], 0.f), 6.f) + cr1.y;
            *(float2*)(Out + off0) = o0;
            *(float2*)(Out + off1) = o1;
        }
    }
}

// ---------------------------------------------------------------------------
// Host launch
// ---------------------------------------------------------------------------
extern "C" void kernel_launch(void* const* d_in, const int* in_sizes, int n_in,
                              void* d_out, int out_size) {
    const float* x   = (const float*)d_in[0];
    const float* Wk  = (const float*)d_in[1];
    const float* Wv  = (const float*)d_in[2];
    const float* Wo  = (const float*)d_in[3];
    const float* cWq = (const float*)d_in[4];
    const float* cbq = (const float*)d_in[5];
    const float* cWv = (const float*)d_in[6];
    const float* cWo = (const float*)d_in[7];
    const float* dww = (const float*)d_in[8];
    const float* bng = (const float*)d_in[9];
    const float* bnb = (const float*)d_in[10];
    const float* bnm = (const float*)d_in[11];
    const float* bnv = (const float*)d_in[12];
    const float* pww = (const float*)d_in[13];
    float* out = (float*)d_out;

    __half* hb = nullptr;
    cudaGetSymbolAddress((void**)&hb, g_hb);
    __half* h0 = hb + (size_t)0 * TOTE;
    __half* h1 = hb + (size_t)1 * TOTE;
    __half* h2 = hb + (size_t)2 * TOTE;
    __half* h3 = hb + (size_t)3 * TOTE;
    __half* h4 = hb + (size_t)4 * TOTE;
    float* crf = nullptr;
    cudaGetSymbolAddress((void**)&crf, g_crf);
    __half* wh = nullptr;
    cudaGetSymbolAddress((void**)&wh, g_wh);
    // slot order: 0=Wk, 1=Wv, 2=cWv, 3=Wo, 4=cWq, 5=cWo, 6=pw
    __half* wKVV = wh;                              // slots 0..2 contiguous
    __half* rWo  = wh + (size_t)3 * 262144;
    __half* rcWq = wh + (size_t)4 * 262144;
    __half* rcWo = wh + (size_t)5 * 262144;
    __half* rpw  = wh + (size_t)6 * 262144;

    const int GEMM_SMEM = 8 * 5120 * 2;             // 81920
    const int CONV_SMEM = (2 * 9216 + 2 * 8704) * 2;
    const int ATTN_SMEM = 3 * 96 * 72 * 2;          // 41472
    cudaFuncSetAttribute(gemm_h, cudaFuncAttributeMaxDynamicSharedMemorySize, GEMM_SMEM);
    cudaFuncSetAttribute(gemm_conv_h, cudaFuncAttributeMaxDynamicSharedMemorySize, CONV_SMEM);
    cudaFuncSetAttribute(attn_h, cudaFuncAttributeMaxDynamicSharedMemorySize, ATTN_SMEM);

    dim3 tb(32, 8);
    dim3 tg(3, 16, 768);

    wprep<<<1792, 256>>>(Wk, Wv, cWv, Wo, cWq, cWo, pww);
    img2seq<<<tg, tb>>>(x, h0);
    // fused: k = h0@Wk^T + h0 -> h1 ; v = h0@Wv^T -> h2 ; kv = h0@cWv^T -> h3
    gemm_h<<<dim3(12, 576), 256, GEMM_SMEM>>>(h0, wKVV, h0, nullptr, h1, h2, h3, 1, 0, 0);
    attn_h<<<dim3(8, 768), 192, ATTN_SMEM>>>(h0, h1, h2, h4);
    gemm_h<<<dim3(4, 576), 256, GEMM_SMEM>>>(h4, rWo, nullptr, nullptr, h1, h1, h1, 0, 0, 0);
    seq2img_hh<<<tg, tb>>>(h1, h2);
    gemm_h<<<dim3(4, 576), 256, GEMM_SMEM>>>(h2, rcWq, nullptr, cbq, h4, h4, h4, 2, 2, 2);
    attn_h<<<dim3(8, 768), 192, ATTN_SMEM>>>(h4, h3, h3, h1);
    gemm_h<<<dim3(4, 576), 256, GEMM_SMEM>>>(h1, rcWo, nullptr, nullptr, h2, h2, h2, 0, 0, 0);
    seq2img_hf<<<tg, tb>>>(h2, crf);
    bnprep<<<2, 256>>>(bng, bnb, bnm, bnv);
    dwconv_bn<<<36864, 256>>>(x, dww, h0);
    gemm_conv_h<<<dim3(72, 4, 8), 256, CONV_SMEM>>>(rpw, h0, crf, out);
}

// round 9
// speedup vs baseline: 5.3738x; 1.0388x over previous
#include <cuda_runtime.h>
#include <cuda_fp16.h>
#include <math.h>
#include <cstdint>

// ---------------------------------------------------------------------------
// Problem constants: B=8, C=512, H=W=96, heads=8, dh=64
// seq layout: [768, 96, 512]  (n = b*96 + w, t = h, channel c)
// ---------------------------------------------------------------------------
#define TOTE 37748736  // 768*96*512

__device__ __half g_hb[5][TOTE];     // fp16 activation buffers
__device__ __half g_dwh[TOTE];       // dwconv output (separate so it can overlap)
__device__ float  g_crf[TOTE];       // cross-attn output (fp32 for final add)
__device__ __half g_wh[7 * 262144];  // fp16 weights: Wk,Wv,cWv,Wo,cWq,cWo,pw
__device__ float  g_bnscale[512];
__device__ float  g_bnbias[512];

__device__ __forceinline__ float fast_exp(float x) {
    x = fmaxf(x, -87.0f);
    float t = x * 1.44269504088896f;
    float fi = floorf(t);
    float f = t - fi;
    float p = 1.54035304e-4f;
    p = fmaf(p, f, 1.33335581e-3f);
    p = fmaf(p, f, 9.61812910e-3f);
    p = fmaf(p, f, 5.55041087e-2f);
    p = fmaf(p, f, 2.40226507e-1f);
    p = fmaf(p, f, 6.93147181e-1f);
    p = fmaf(p, f, 1.0f);
    return p * __int_as_float(((int)fi + 127) << 23);
}

#define MMA_F16(c0,c1,c2,c3,a0,a1,a2,a3,b0,b1) \
    asm volatile("mma.sync.aligned.m16n8k16.row.col.f32.f16.f16.f32 " \
                 "{%0,%1,%2,%3},{%4,%5,%6,%7},{%8,%9},{%0,%1,%2,%3};" \
                 : "+f"(c0),"+f"(c1),"+f"(c2),"+f"(c3) \
                 : "r"(a0),"r"(a1),"r"(a2),"r"(a3),"r"(b0),"r"(b1))

#define LDSM_X4(r0,r1,r2,r3,addr) \
    asm volatile("ldmatrix.sync.aligned.m8n8.x4.shared.b16 {%0,%1,%2,%3}, [%4];" \
                 : "=r"(r0),"=r"(r1),"=r"(r2),"=r"(r3) : "r"(addr))

#define LDSM_X4T(r0,r1,r2,r3,addr) \
    asm volatile("ldmatrix.sync.aligned.m8n8.x4.trans.shared.b16 {%0,%1,%2,%3}, [%4];" \
                 : "=r"(r0),"=r"(r1),"=r"(r2),"=r"(r3) : "r"(addr))

#define CP16(dst, src) \
    asm volatile("cp.async.cg.shared.global [%0], [%1], 16;" :: "r"(dst), "l"(src))
#define CP_COMMIT() asm volatile("cp.async.commit_group;")
#define CP_WAIT0()  asm volatile("cp.async.wait_group 0;")
#define CP_WAIT2()  asm volatile("cp.async.wait_group 2;")

__device__ __forceinline__ unsigned h2pack(float a, float b) {
    unsigned r;
    asm("cvt.rn.f16x2.f32 %0, %2, %1;" : "=r"(r) : "f"(a), "f"(b));
    return r;
}

// ---------------------------------------------------------------------------
// Weight prep: fp16-round 7 [512x512] matrices into g_wh (slot order = arg order)
// ---------------------------------------------------------------------------
__global__ void wprep(const float* __restrict__ a0, const float* __restrict__ a1,
                      const float* __restrict__ a2, const float* __restrict__ a3,
                      const float* __restrict__ a4, const float* __restrict__ a5,
                      const float* __restrict__ a6) {
    int i = blockIdx.x * 256 + threadIdx.x;
    int mat = i >> 16;
    int off = (i & 65535) * 4;
    const float* s;
    switch (mat) {
        case 0: s = a0; break; case 1: s = a1; break; case 2: s = a2; break;
        case 3: s = a3; break; case 4: s = a4; break; case 5: s = a5; break;
        default: s = a6; break;
    }
    float4 v = *(const float4*)(s + off);
    *(__half2*)(g_wh + (size_t)mat * 262144 + off)     = __floats2half2_rn(v.x, v.y);
    *(__half2*)(g_wh + (size_t)mat * 262144 + off + 2) = __floats2half2_rn(v.z, v.w);
}

// ---------------------------------------------------------------------------
// Layout transposes (c <-> w per (b,h) plane)
// ---------------------------------------------------------------------------
__global__ void img2seq(const float* __restrict__ img, __half* __restrict__ seq) {
    __shared__ float tile[32][33];
    int bh = blockIdx.z;
    int b = bh / 96, h = bh % 96;
    int c0 = blockIdx.y * 32, w0 = blockIdx.x * 32;
    int tx = threadIdx.x, ty = threadIdx.y;
#pragma unroll
    for (int i = 0; i < 4; i++) {
        int c = c0 + ty + i * 8;
        tile[ty + i * 8][tx] = img[(((size_t)b * 512 + c) * 96 + h) * 96 + w0 + tx];
    }
    __syncthreads();
#pragma unroll
    for (int i = 0; i < 4; i++) {
        int w = w0 + ty + i * 8;
        seq[(((size_t)(b * 96 + w)) * 96 + h) * 512 + c0 + tx] =
            __float2half_rn(tile[tx][ty + i * 8]);
    }
}

__global__ void seq2img_hh(const __half* __restrict__ seq, __half* __restrict__ img) {
    __shared__ __half tile[32][33];
    int bh = blockIdx.z;
    int b = bh / 96, h = bh % 96;
    int c0 = blockIdx.y * 32, w0 = blockIdx.x * 32;
    int tx = threadIdx.x, ty = threadIdx.y;
#pragma unroll
    for (int i = 0; i < 4; i++) {
        int w = w0 + ty + i * 8;
        tile[ty + i * 8][tx] = seq[(((size_t)(b * 96 + w)) * 96 + h) * 512 + c0 + tx];
    }
    __syncthreads();
#pragma unroll
    for (int i = 0; i < 4; i++) {
        int c = c0 + ty + i * 8;
        img[(((size_t)b * 512 + c) * 96 + h) * 96 + w0 + tx] = tile[tx][ty + i * 8];
    }
}

__global__ void seq2img_hf(const __half* __restrict__ seq, float* __restrict__ img) {
    __shared__ float tile[32][33];
    int bh = blockIdx.z;
    int b = bh / 96, h = bh % 96;
    int c0 = blockIdx.y * 32, w0 = blockIdx.x * 32;
    int tx = threadIdx.x, ty = threadIdx.y;
#pragma unroll
    for (int i = 0; i < 4; i++) {
        int w = w0 + ty + i * 8;
        tile[ty + i * 8][tx] =
            __half2float(seq[(((size_t)(b * 96 + w)) * 96 + h) * 512 + c0 + tx]);
    }
    __syncthreads();
#pragma unroll
    for (int i = 0; i < 4; i++) {
        int c = c0 + ty + i * 8;
        img[(((size_t)b * 512 + c) * 96 + h) * 96 + w0 + tx] = tile[tx][ty + i * 8];
    }
}

// ---------------------------------------------------------------------------
// fp16 GEMM, multi-output (unchanged, passing).
// ---------------------------------------------------------------------------
__global__ __launch_bounds__(256, 2) void gemm_h(
    const __half* __restrict__ A, const __half* __restrict__ Wb,
    const __half* __restrict__ Add, const float* __restrict__ bias,
    __half* __restrict__ o0, __half* __restrict__ o1, __half* __restrict__ o2,
    int mode0, int mode1, int mode2)
{
    extern __shared__ char smc[];
    unsigned sa = (unsigned)__cvta_generic_to_shared(smc);
    unsigned sw = sa + 40960;          // 4 stages x 5120 halves x 2B
    int m0 = blockIdx.y * 128;
    int nmat = blockIdx.x >> 2;
    int ncol0 = (blockIdx.x & 3) * 128;
    const __half* Wp = Wb + (size_t)blockIdx.x * 128 * 512;
    __half* Cout; int mode;
    if (nmat == 0)      { Cout = o0; mode = mode0; }
    else if (nmat == 1) { Cout = o1; mode = mode1; }
    else                { Cout = o2; mode = mode2; }

    int tid = threadIdx.x;
    int w = tid >> 5, l = tid & 31;
    int g = l >> 2, t = l & 3;
    int wm = (w & 1) * 64, wn = (w >> 1) * 32;
    int u = tid & 3, r0 = tid >> 2;    // 16B chunk, row 0..63

    int p = l & 7, sel = l >> 3;
    unsigned a_off = (unsigned)(((wm + p + (sel & 1) * 8) * 40 + (sel >> 1) * 8) * 2);
    unsigned b_off = (unsigned)(((p + (sel & 1) * 8) * 40 + (sel >> 1) * 8) * 2);

    float c[4][4][4];
#pragma unroll
    for (int mi = 0; mi < 4; mi++)
#pragma unroll
        for (int ni = 0; ni < 4; ni++)
#pragma unroll
            for (int r = 0; r < 4; r++) c[mi][ni][r] = 0.f;

#define GH_LOAD(st, kc) do { \
    const __half* Ag = A  + (size_t)(m0 + r0) * 512 + (kc) * 32 + u * 8; \
    const __half* Wg = Wp + (size_t)r0 * 512 + (kc) * 32 + u * 8; \
    unsigned da = sa + (unsigned)((st) * 10240 + (r0 * 40 + u * 8) * 2); \
    unsigned dw = sw + (unsigned)((st) * 10240 + (r0 * 40 + u * 8) * 2); \
    CP16(da, Ag); CP16(da + 5120, Ag + (size_t)64 * 512); \
    CP16(dw, Wg); CP16(dw + 5120, Wg + (size_t)64 * 512); \
    CP_COMMIT(); } while (0)

    GH_LOAD(0, 0); GH_LOAD(1, 1); GH_LOAD(2, 2);
#pragma unroll 1
    for (int kt = 0; kt < 16; kt++) {
        int cur = kt & 3;
        CP_WAIT2();
        __syncthreads();
        if (kt < 13) { GH_LOAD((kt + 3) & 3, kt + 3); } else { CP_COMMIT(); }
        unsigned cb = (unsigned)(cur * 10240);
#pragma unroll
        for (int ks = 0; ks < 2; ks++) {
            unsigned kofs = (unsigned)(ks * 32);
            unsigned a[4][4];
#pragma unroll
            for (int mi = 0; mi < 4; mi++) {
                unsigned addr = sa + cb + a_off + (unsigned)(mi * 16 * 80) + kofs;
                LDSM_X4(a[mi][0], a[mi][1], a[mi][2], a[mi][3], addr);
            }
            unsigned b[4][2];
#pragma unroll
            for (int nj = 0; nj < 2; nj++) {
                unsigned addr = sw + cb + b_off + (unsigned)((wn + nj * 16) * 80) + kofs;
                unsigned q0, q1, q2, q3;
                LDSM_X4(q0, q1, q2, q3, addr);
                b[nj * 2][0] = q0;     b[nj * 2][1] = q2;
                b[nj * 2 + 1][0] = q1; b[nj * 2 + 1][1] = q3;
            }
#pragma unroll
            for (int mi = 0; mi < 4; mi++)
#pragma unroll
                for (int ni = 0; ni < 4; ni++)
                    MMA_F16(c[mi][ni][0], c[mi][ni][1], c[mi][ni][2], c[mi][ni][3],
                            a[mi][0], a[mi][1], a[mi][2], a[mi][3],
                            b[ni][0], b[ni][1]);
        }
    }
#undef GH_LOAD

#pragma unroll
    for (int mi = 0; mi < 4; mi++) {
#pragma unroll
        for (int ni = 0; ni < 4; ni++) {
            int m = m0 + wm + mi * 16 + g;
            int n = ncol0 + wn + ni * 8 + 2 * t;
            float v00 = c[mi][ni][0], v01 = c[mi][ni][1];
            float v10 = c[mi][ni][2], v11 = c[mi][ni][3];
            if (mode == 1) {
                float2 a0 = __half22float2(*(const __half2*)(Add + (size_t)m * 512 + n));
                float2 a1 = __half22float2(*(const __half2*)(Add + (size_t)(m + 8) * 512 + n));
                v00 += a0.x; v01 += a0.y; v10 += a1.x; v11 += a1.y;
            } else if (mode == 2) {
                float2 bb = *(const float2*)(bias + n);
                v00 += bb.x; v01 += bb.y; v10 += bb.x; v11 += bb.y;
            }
            *(__half2*)(Cout + (size_t)m * 512 + n) = __floats2half2_rn(v00, v01);
            *(__half2*)(Cout + (size_t)(m + 8) * 512 + n) = __floats2half2_rn(v10, v11);
        }
    }
}

// ---------------------------------------------------------------------------
// fp16 tensor-core attention: block per (n,head), 192 threads (6 warps).
// cp.async loads; occupancy 4 (reg cap 85); V aliases K when Kg==Vg.
// ---------------------------------------------------------------------------
__global__ __launch_bounds__(192, 4) void attn_h(
    const __half* __restrict__ Qg, const __half* __restrict__ Kg,
    const __half* __restrict__ Vg, __half* __restrict__ Og)
{
    extern __shared__ char smc[];
    unsigned sq = (unsigned)__cvta_generic_to_shared(smc);     // Q [96][72]
    unsigned sk = sq + 96 * 72 * 2;                            // K [96][72]
    unsigned sv0 = sk + 96 * 72 * 2;                           // V [96][72]

    int hd = blockIdx.x, n = blockIdx.y;
    size_t base = (size_t)n * 96 * 512 + hd * 64;
    int tid = threadIdx.x;
    int w = tid >> 5, l = tid & 31;
    int g = l >> 2, t = l & 3;
    int qr = w * 16;
    int p = l & 7, sel = l >> 3;

    bool kv_same = (Kg == Vg);
    unsigned sv = kv_same ? sk : sv0;

    for (int i = tid; i < 768; i += 192) {
        int r = i >> 3;
        unsigned d = (unsigned)((r * 72 + (i & 7) * 8) * 2);
        size_t goff = base + (size_t)r * 512 + (i & 7) * 8;
        CP16(sq + d, Qg + goff);
        CP16(sk + d, Kg + goff);
        if (!kv_same) CP16(sv0 + d, Vg + goff);
    }
    CP_COMMIT();
    CP_WAIT0();
    __syncthreads();

    // ---- S = Q K^T : c[12][4] covers 16 q-rows x 96 kv-cols ----
    float c[12][4];
#pragma unroll
    for (int ni = 0; ni < 12; ni++)
#pragma unroll
        for (int r = 0; r < 4; r++) c[ni][r] = 0.f;

    unsigned aq_off = (unsigned)(((qr + p + (sel & 1) * 8) * 72 + (sel >> 1) * 8) * 2);
    unsigned bk_off = (unsigned)(((p + (sel & 1) * 8) * 72 + (sel >> 1) * 8) * 2);

#pragma unroll
    for (int ks = 0; ks < 4; ks++) {           // k = dh, 4 steps of 16
        unsigned kofs = (unsigned)(ks * 32);
        unsigned a0, a1, a2, a3;
        LDSM_X4(a0, a1, a2, a3, sq + aq_off + kofs);
#pragma unroll
        for (int nj = 0; nj < 6; nj++) {       // kv rows, 6 tiles of 16
            unsigned addr = sk + bk_off + (unsigned)(nj * 16 * 144) + kofs;
            unsigned q0, q1, q2, q3;
            LDSM_X4(q0, q1, q2, q3, addr);
            MMA_F16(c[2*nj][0], c[2*nj][1], c[2*nj][2], c[2*nj][3],
                    a0, a1, a2, a3, q0, q2);
            MMA_F16(c[2*nj+1][0], c[2*nj+1][1], c[2*nj+1][2], c[2*nj+1][3],
                    a0, a1, a2, a3, q1, q3);
        }
    }

    // ---- softmax over kv (rows qr+g and qr+g+8) ----
    float m0 = -1e30f, m1 = -1e30f;
#pragma unroll
    for (int ni = 0; ni < 12; ni++) {
#pragma unroll
        for (int r = 0; r < 4; r++) c[ni][r] *= 0.125f;
        m0 = fmaxf(m0, fmaxf(c[ni][0], c[ni][1]));
        m1 = fmaxf(m1, fmaxf(c[ni][2], c[ni][3]));
    }
    m0 = fmaxf(m0, __shfl_xor_sync(0xffffffff, m0, 1));
    m0 = fmaxf(m0, __shfl_xor_sync(0xffffffff, m0, 2));
    m1 = fmaxf(m1, __shfl_xor_sync(0xffffffff, m1, 1));
    m1 = fmaxf(m1, __shfl_xor_sync(0xffffffff, m1, 2));
    float s0 = 0.f, s1 = 0.f;
#pragma unroll
    for (int ni = 0; ni < 12; ni++) {
        c[ni][0] = fast_exp(c[ni][0] - m0);
        c[ni][1] = fast_exp(c[ni][1] - m0);
        c[ni][2] = fast_exp(c[ni][2] - m1);
        c[ni][3] = fast_exp(c[ni][3] - m1);
        s0 += c[ni][0] + c[ni][1];
        s1 += c[ni][2] + c[ni][3];
    }
    s0 += __shfl_xor_sync(0xffffffff, s0, 1);
    s0 += __shfl_xor_sync(0xffffffff, s0, 2);
    s1 += __shfl_xor_sync(0xffffffff, s1, 1);
    s1 += __shfl_xor_sync(0xffffffff, s1, 2);

    // ---- pack ALL of P now; c dies here ----
    unsigned ph[24];
#pragma unroll
    for (int ni = 0; ni < 12; ni++) {
        ph[2 * ni]     = h2pack(c[ni][0], c[ni][1]);
        ph[2 * ni + 1] = h2pack(c[ni][2], c[ni][3]);
    }

    // ---- O = P V ----
    float o[8][4];
#pragma unroll
    for (int ni = 0; ni < 8; ni++)
#pragma unroll
        for (int r = 0; r < 4; r++) o[ni][r] = 0.f;

    unsigned bv_off = (unsigned)(((p + (sel & 1) * 8) * 72 + (sel >> 1) * 8) * 2);
#pragma unroll
    for (int ks = 0; ks < 6; ks++) {           // kv, 6 steps of 16
        unsigned a0 = ph[4 * ks + 0];
        unsigned a1 = ph[4 * ks + 1];
        unsigned a2 = ph[4 * ks + 2];
        unsigned a3 = ph[4 * ks + 3];
#pragma unroll
        for (int nj = 0; nj < 4; nj++) {       // dh cols, 4 tiles of 16
            unsigned addr = sv + bv_off + (unsigned)(ks * 16 * 144 + nj * 32);
            unsigned q0, q1, q2, q3;
            LDSM_X4T(q0, q1, q2, q3, addr);
            MMA_F16(o[2*nj][0], o[2*nj][1], o[2*nj][2], o[2*nj][3],
                    a0, a1, a2, a3, q0, q1);
            MMA_F16(o[2*nj+1][0], o[2*nj+1][1], o[2*nj+1][2], o[2*nj+1][3],
                    a0, a1, a2, a3, q2, q3);
        }
    }

    float inv0 = 1.0f / s0, inv1 = 1.0f / s1;
    __half* ob = Og + base;
#pragma unroll
    for (int ni = 0; ni < 8; ni++) {
        *(__half2*)(ob + (size_t)(qr + g) * 512 + ni * 8 + 2 * t) =
            __floats2half2_rn(o[ni][0] * inv0, o[ni][1] * inv0);
        *(__half2*)(ob + (size_t)(qr + g + 8) * 512 + ni * 8 + 2 * t) =
            __floats2half2_rn(o[ni][2] * inv1, o[ni][3] * inv1);
    }
}

// ---------------------------------------------------------------------------
__global__ void bnprep(const float* __restrict__ g, const float* __restrict__ b,
                       const float* __restrict__ m, const float* __restrict__ v) {
    int c = blockIdx.x * 256 + threadIdx.x;
    if (c < 512) {
        float sc = g[c] * rsqrtf(v[c] + 1e-5f);
        g_bnscale[c] = sc;
        g_bnbias[c]  = b[c] - m[c] * sc;
    }
}

// depthwise 3x3 + BN, 4 outputs per thread along w (float4 row loads)
__global__ void dwconv_bn(const float* __restrict__ x, const float* __restrict__ wd,
                          __half* __restrict__ o) {
    int idx = blockIdx.x * 256 + threadIdx.x;
    int wg = idx % 24;
    int t = idx / 24;
    int h = t % 96;
    int bc = t / 96;
    int c = bc & 511;
    int w0 = wg * 4;
    const float* wt = wd + c * 9;
    const float* xp = x + (size_t)bc * 9216;
    float acc[4] = {0.f, 0.f, 0.f, 0.f};
#pragma unroll
    for (int kh = 0; kh < 3; kh++) {
        int hh = h + kh - 1;
        if (hh < 0 || hh >= 96) continue;
        const float* row = xp + hh * 96;
        float4 v = *(const float4*)(row + w0);
        float left  = (w0 > 0)  ? row[w0 - 1] : 0.f;
        float right = (w0 < 92) ? row[w0 + 4] : 0.f;
        float vals[6] = {left, v.x, v.y, v.z, v.w, right};
        float wa = wt[kh * 3 + 0], wb = wt[kh * 3 + 1], wc = wt[kh * 3 + 2];
#pragma unroll
        for (int j = 0; j < 4; j++)
            acc[j] = fmaf(vals[j], wa, fmaf(vals[j + 1], wb, fmaf(vals[j + 2], wc, acc[j])));
    }
    float sc = g_bnscale[c], bb = g_bnbias[c];
    __half* op = o + (size_t)bc * 9216 + h * 96 + w0;
    *(__half2*)op       = __floats2half2_rn(fmaf(acc[0], sc, bb), fmaf(acc[1], sc, bb));
    *(__half2*)(op + 2) = __floats2half2_rn(fmaf(acc[2], sc, bb), fmaf(acc[3], sc, bb));
}

// ---------------------------------------------------------------------------
// fp16 1x1-conv GEMM per batch (unchanged, passing): Out = clip(pw@y)+CR
// ---------------------------------------------------------------------------
__global__ __launch_bounds__(256, 2) void gemm_conv_h(
    const __half* __restrict__ Apw, const __half* __restrict__ Bt,
    const float* __restrict__ CR, float* __restrict__ Out)
{
    extern __shared__ char smc[];
    __half* As = (__half*)smc;
    __half* Bs = (__half*)(smc + 36864);
    int bat = blockIdx.z;
    size_t boff = (size_t)bat * 512 * 9216;
    const __half* Bg = Bt + boff;
    int n0 = blockIdx.x * 128;
    int m0 = blockIdx.y * 128;
    int tid = threadIdx.x;
    int w = tid >> 5, l = tid & 31;
    int g = l >> 2, t = l & 3;
    int wm = (w & 1) * 64, wn = (w >> 1) * 32;

    int uA = tid & 7, rA = tid >> 3;
    int uB = tid & 15, rB = tid >> 4;

    unsigned sa = (unsigned)__cvta_generic_to_shared(As);
    unsigned sb = (unsigned)__cvta_generic_to_shared(Bs);
    int p = l & 7, sel = l >> 3;
    unsigned a_off = (unsigned)(((wm + p + (sel & 1) * 8) * 72 + (sel >> 1) * 8) * 2);
    unsigned b_off = (unsigned)(((p + (sel & 1) * 8) * 136 + (sel >> 1) * 8) * 2);

    float c[4][4][4];
#pragma unroll
    for (int mi = 0; mi < 4; mi++)
#pragma unroll
        for (int ni = 0; ni < 4; ni++)
#pragma unroll
            for (int r = 0; r < 4; r++) c[mi][ni][r] = 0.f;

#define GC_LOAD(st, kc) do { \
    const __half* Ag = Apw + (size_t)(m0 + rA) * 512 + (kc) * 64 + uA * 8; \
    unsigned da = sa + (unsigned)(((st) * 9216 + rA * 72 + uA * 8) * 2); \
    _Pragma("unroll") \
    for (int i = 0; i < 4; i++) \
        CP16(da + (unsigned)(i * 32 * 144), Ag + (size_t)i * 32 * 512); \
    const __half* Bgp = Bg + (size_t)((kc) * 64 + rB) * 9216 + n0 + uB * 8; \
    unsigned db = sb + (unsigned)(((st) * 8704 + rB * 136 + uB * 8) * 2); \
    _Pragma("unroll") \
    for (int i = 0; i < 4; i++) \
        CP16(db + (unsigned)(i * 16 * 272), Bgp + (size_t)i * 16 * 9216); \
    CP_COMMIT(); } while (0)

    GC_LOAD(0, 0);
#pragma unroll 1
    for (int kt = 0; kt < 8; kt++) {
        int cur = kt & 1;
        CP_WAIT0();
        __syncthreads();
        if (kt < 7) GC_LOAD(cur ^ 1, kt + 1);
        unsigned abase = sa + (unsigned)(cur * 9216 * 2) + a_off;
        unsigned bbase = sb + (unsigned)(cur * 8704 * 2) + b_off;
#pragma unroll
        for (int ks = 0; ks < 4; ks++) {
            int k0 = ks * 16;
            unsigned a[4][4];
#pragma unroll
            for (int mi = 0; mi < 4; mi++) {
                unsigned addr = abase + (unsigned)((mi * 16 * 72 + k0) * 2);
                LDSM_X4(a[mi][0], a[mi][1], a[mi][2], a[mi][3], addr);
            }
            unsigned b[4][2];
#pragma unroll
            for (int nj = 0; nj < 2; nj++) {
                unsigned addr = bbase + (unsigned)((k0 * 136 + wn + nj * 16) * 2);
                unsigned q0, q1, q2, q3;
                LDSM_X4T(q0, q1, q2, q3, addr);
                b[nj * 2][0] = q0;     b[nj * 2][1] = q1;
                b[nj * 2 + 1][0] = q2; b[nj * 2 + 1][1] = q3;
            }
#pragma unroll
            for (int mi = 0; mi < 4; mi++)
#pragma unroll
                for (int ni = 0; ni < 4; ni++)
                    MMA_F16(c[mi][ni][0], c[mi][ni][1], c[mi][ni][2], c[mi][ni][3],
                            a[mi][0], a[mi][1], a[mi][2], a[mi][3],
                            b[ni][0], b[ni][1]);
        }
        __syncthreads();
    }
#undef GC_LOAD

#pragma unroll
    for (int mi = 0; mi < 4; mi++) {
#pragma unroll
        for (int ni = 0; ni < 4; ni++) {
            int m = m0 + wm + mi * 16 + g;
            int n = n0 + wn + ni * 8 + 2 * t;
            size_t off0 = boff + (size_t)m * 9216 + n;
            size_t off1 = boff + (size_t)(m + 8) * 9216 + n;
            float2 cr0 = *(const float2*)(CR + off0);
            float2 cr1 = *(const float2*)(CR + off1);
            float2 o0, o1;
            o0.x = fminf(fmaxf(c[mi][ni][0], 0.f), 6.f) + cr0.x;
            o0.y = fminf(fmaxf(c[mi][ni][1], 0.f), 6.f) + cr0.y;
            o1.x = fminf(fmaxf(c[mi][ni][2], 0.f), 6.f) + cr1.x;
            o1.y = fminf(fmaxf(c[mi][ni][3], 0.f), 6.f) + cr1.y;
            *(float2*)(Out + off0) = o0;
            *(float2*)(Out + off1) = o1;
        }
    }
}

// ---------------------------------------------------------------------------
// Host launch — conv branch forked onto a second stream (capturable fork/join)
// ---------------------------------------------------------------------------
extern "C" void kernel_launch(void* const* d_in, const int* in_sizes, int n_in,
                              void* d_out, int out_size) {
    const float* x   = (const float*)d_in[0];
    const float* Wk  = (const float*)d_in[1];
    const float* Wv  = (const float*)d_in[2];
    const float* Wo  = (const float*)d_in[3];
    const float* cWq = (const float*)d_in[4];
    const float* cbq = (const float*)d_in[5];
    const float* cWv = (const float*)d_in[6];
    const float* cWo = (const float*)d_in[7];
    const float* dww = (const float*)d_in[8];
    const float* bng = (const float*)d_in[9];
    const float* bnb = (const float*)d_in[10];
    const float* bnm = (const float*)d_in[11];
    const float* bnv = (const float*)d_in[12];
    const float* pww = (const float*)d_in[13];
    float* out = (float*)d_out;

    __half* hb = nullptr;
    cudaGetSymbolAddress((void**)&hb, g_hb);
    __half* h0 = hb + (size_t)0 * TOTE;
    __half* h1 = hb + (size_t)1 * TOTE;
    __half* h2 = hb + (size_t)2 * TOTE;
    __half* h3 = hb + (size_t)3 * TOTE;
    __half* h4 = hb + (size_t)4 * TOTE;
    __half* dwh = nullptr;
    cudaGetSymbolAddress((void**)&dwh, g_dwh);
    float* crf = nullptr;
    cudaGetSymbolAddress((void**)&crf, g_crf);
    __half* wh = nullptr;
    cudaGetSymbolAddress((void**)&wh, g_wh);
    __half* wKVV = wh;                              // slots 0..2 contiguous
    __half* rWo  = wh + (size_t)3 * 262144;
    __half* rcWq = wh + (size_t)4 * 262144;
    __half* rcWo = wh + (size_t)5 * 262144;
    __half* rpw  = wh + (size_t)6 * 262144;

    const int GEMM_SMEM = 8 * 5120 * 2;             // 81920
    const int CONV_SMEM = (2 * 9216 + 2 * 8704) * 2;
    const int ATTN_SMEM = 3 * 96 * 72 * 2;          // 41472
    cudaFuncSetAttribute(gemm_h, cudaFuncAttributeMaxDynamicSharedMemorySize, GEMM_SMEM);
    cudaFuncSetAttribute(gemm_conv_h, cudaFuncAttributeMaxDynamicSharedMemorySize, CONV_SMEM);
    cudaFuncSetAttribute(attn_h, cudaFuncAttributeMaxDynamicSharedMemorySize, ATTN_SMEM);

    // Side stream + events: created once, host-side, outside any capture.
    static cudaStream_t s2 = nullptr;
    static cudaEvent_t evFork = nullptr, evW = nullptr, evDw = nullptr;
    if (!s2) {
        cudaStreamCreateWithFlags(&s2, cudaStreamNonBlocking);
        cudaEventCreateWithFlags(&evFork, cudaEventDisableTiming);
        cudaEventCreateWithFlags(&evW, cudaEventDisableTiming);
        cudaEventCreateWithFlags(&evDw, cudaEventDisableTiming);
    }

    dim3 tb(32, 8);
    dim3 tg(3, 16, 768);

    // ---- fork: weight prep + conv branch on s2 ----
    cudaEventRecord(evFork, 0);
    cudaStreamWaitEvent(s2, evFork, 0);
    wprep<<<1792, 256, 0, s2>>>(Wk, Wv, cWv, Wo, cWq, cWo, pww);
    cudaEventRecord(evW, s2);
    bnprep<<<2, 256, 0, s2>>>(bng, bnb, bnm, bnv);
    dwconv_bn<<<36864, 256, 0, s2>>>(x, dww, dwh);
    cudaEventRecord(evDw, s2);

    // ---- main chain ----
    img2seq<<<tg, tb>>>(x, h0);
    cudaStreamWaitEvent(0, evW, 0);   // weights ready
    gemm_h<<<dim3(12, 576), 256, GEMM_SMEM>>>(h0, wKVV, h0, nullptr, h1, h2, h3, 1, 0, 0);
    attn_h<<<dim3(8, 768), 192, ATTN_SMEM>>>(h0, h1, h2, h4);
    gemm_h<<<dim3(4, 576), 256, GEMM_SMEM>>>(h4, rWo, nullptr, nullptr, h1, h1, h1, 0, 0, 0);
    seq2img_hh<<<tg, tb>>>(h1, h2);
    gemm_h<<<dim3(4, 576), 256, GEMM_SMEM>>>(h2, rcWq, nullptr, cbq, h4, h4, h4, 2, 2, 2);
    attn_h<<<dim3(8, 768), 192, ATTN_SMEM>>>(h4, h3, h3, h1);
    gemm_h<<<dim3(4, 576), 256, GEMM_SMEM>>>(h1, rcWo, nullptr, nullptr, h2, h2, h2, 0, 0, 0);
    seq2img_hf<<<tg, tb>>>(h2, crf);
    cudaStreamWaitEvent(0, evDw, 0);  // dwconv output ready
    gemm_conv_h<<<dim3(72, 4, 8), 256, CONV_SMEM>>>(rpw, dwh, crf, out);
}